// round 4
// baseline (speedup 1.0000x reference)
#include <cuda_runtime.h>

#define SQ 1024
#define NB 8
#define NE 512
#define NH 8
#define QHD 32
#define PHD 4
#define PDIM 192
#define NPOS (2*SQ-1)   // 2047
#define INPROJ 544

// Scratch (device globals; no allocations allowed)
__device__ __align__(16) float g_q[NH*NB*SQ*QHD];   // [h][b][s][d]
__device__ __align__(16) float g_k[NH*NB*SQ*QHD];   // [h][b][s][d]
__device__ __align__(16) float g_p[NH*NB*SQ*PHD];   // [h][b][s][d]
__device__ __align__(16) float4 g_pe[NH*NPOS];      // [h][n] (4 dims packed)

// ---------------------------------------------------------------------------
// Kernel 1: proj = x @ W^T + b -> g_q/g_k/g_p.
// M=8192, N=544 (5 tiles of 128), K=512. Tile 128x128x16, 256 thr, 8x8/thread
// in split form (rows ty*4 / 64+ty*4, cols tx*4 / 64+tx*4): 64 FFMA per
// 4 LDS.128, a-loads broadcast, b-loads conflict-free.
// ---------------------------------------------------------------------------
__global__ __launch_bounds__(256, 2) void proj_kernel(
    const float* __restrict__ x, const float* __restrict__ w,
    const float* __restrict__ bias)
{
    __shared__ float As[16][132];
    __shared__ float Bs[16][132];
    const int tid = threadIdx.x;
    const int tx = tid & 15, ty = tid >> 4;
    const int m0 = blockIdx.y * 128;
    const int n0 = blockIdx.x * 128;

    const int lrow = tid >> 1;          // 0..127
    const int kh   = (tid & 1) * 8;     // 0 or 8

    const float4* xr = (const float4*)&x[(size_t)(m0 + lrow)*NE];
    const int nb = n0 + lrow;
    const bool bval = (nb < INPROJ);
    const float4* wr = bval ? (const float4*)&w[(size_t)nb*NE] : (const float4*)w;

    float acc[8][8];
#pragma unroll
    for (int i = 0; i < 8; ++i)
#pragma unroll
        for (int j = 0; j < 8; ++j) acc[i][j] = 0.f;

    for (int kt = 0; kt < 32; ++kt) {
        float4 av0 = xr[kt*4 + (kh >> 2)];
        float4 av1 = xr[kt*4 + (kh >> 2) + 1];
        float4 bv0 = make_float4(0.f,0.f,0.f,0.f);
        float4 bv1 = make_float4(0.f,0.f,0.f,0.f);
        if (bval) { bv0 = wr[kt*4 + (kh >> 2)]; bv1 = wr[kt*4 + (kh >> 2) + 1]; }
        __syncthreads();
        As[kh+0][lrow] = av0.x; As[kh+1][lrow] = av0.y;
        As[kh+2][lrow] = av0.z; As[kh+3][lrow] = av0.w;
        As[kh+4][lrow] = av1.x; As[kh+5][lrow] = av1.y;
        As[kh+6][lrow] = av1.z; As[kh+7][lrow] = av1.w;
        Bs[kh+0][lrow] = bv0.x; Bs[kh+1][lrow] = bv0.y;
        Bs[kh+2][lrow] = bv0.z; Bs[kh+3][lrow] = bv0.w;
        Bs[kh+4][lrow] = bv1.x; Bs[kh+5][lrow] = bv1.y;
        Bs[kh+6][lrow] = bv1.z; Bs[kh+7][lrow] = bv1.w;
        __syncthreads();
#pragma unroll
        for (int k = 0; k < 16; ++k) {
            float4 a0 = *(const float4*)&As[k][ty*4];
            float4 a1 = *(const float4*)&As[k][64 + ty*4];
            float4 b0 = *(const float4*)&Bs[k][tx*4];
            float4 b1 = *(const float4*)&Bs[k][64 + tx*4];
            float ar[8] = {a0.x,a0.y,a0.z,a0.w, a1.x,a1.y,a1.z,a1.w};
            float br[8] = {b0.x,b0.y,b0.z,b0.w, b1.x,b1.y,b1.z,b1.w};
#pragma unroll
            for (int i = 0; i < 8; ++i)
#pragma unroll
                for (int j = 0; j < 8; ++j)
                    acc[i][j] = fmaf(ar[i], br[j], acc[i][j]);
        }
    }

#pragma unroll
    for (int ii = 0; ii < 2; ++ii) {
#pragma unroll
        for (int i = 0; i < 4; ++i) {
            int m = m0 + ii*64 + ty*4 + i;
            int s = m >> 3, b = m & 7;
#pragma unroll
            for (int jj = 0; jj < 2; ++jj) {
#pragma unroll
                for (int j = 0; j < 4; ++j) {
                    int n = n0 + jj*64 + tx*4 + j;
                    if (n >= INPROJ) continue;
                    float v = acc[ii*4+i][jj*4+j] + __ldg(&bias[n]);
                    if (n < 256) {
                        int h = n >> 5, d = n & 31;
                        g_q[(((h<<3)+b)*SQ + s)*QHD + d] = v;
                    } else if (n < 512) {
                        int n2 = n - 256; int h = n2 >> 5, d = n2 & 31;
                        g_k[(((h<<3)+b)*SQ + s)*QHD + d] = v;
                    } else {
                        int n3 = n - 512; int h = n3 >> 2, d = n3 & 3;
                        g_p[(((h<<3)+b)*SQ + s)*PHD + d] = v;
                    }
                }
            }
        }
    }
}

// ---------------------------------------------------------------------------
// Kernel 2: g_pe[h][n][0..3] = sum_p pos_emb[n][p] * linear_pos_w[h*4+d][p]
// ---------------------------------------------------------------------------
__global__ __launch_bounds__(256) void pe_kernel(
    const float* __restrict__ pos_emb, const float* __restrict__ lw)
{
    __shared__ float ws[32*193];
    const int tid = threadIdx.x;
    for (int i = tid; i < 32*PDIM; i += 256) {
        int o = i / PDIM, p = i % PDIM;
        ws[o*193 + p] = lw[i];
    }
    __syncthreads();
    int idx = blockIdx.x * 256 + tid;
    if (idx >= NPOS*NH) return;
    int n = idx >> 3, h = idx & 7;
    float a0 = 0.f, a1 = 0.f, a2 = 0.f, a3 = 0.f;
    const float* pr = &pos_emb[(size_t)n*PDIM];
#pragma unroll 4
    for (int p = 0; p < PDIM; ++p) {
        float pv = __ldg(&pr[p]);
        a0 = fmaf(pv, ws[(h*4+0)*193 + p], a0);
        a1 = fmaf(pv, ws[(h*4+1)*193 + p], a1);
        a2 = fmaf(pv, ws[(h*4+2)*193 + p], a2);
        a3 = fmaf(pv, ws[(h*4+3)*193 + p], a3);
    }
    g_pe[h*NPOS + n] = make_float4(a0, a1, a2, a3);
}

// ---------------------------------------------------------------------------
// Kernel 3: fused scores + rel-shift + mask + softmax.
// Block: 32 q-rows x all 1024 j, one (h,b). 512 threads, 16 warps.
// Warp w owns j in [w*64, w*64+64); thread owns j0=w*64+lane and j1=j0+32,
// and ALL 32 rows -> acc[32][2]. K panel transposed in smem: k_t[d][j].
// Per 4 k-dims: 8 conflict-free scalar k loads + 32 broadcast q float4 loads
// feed 256 FFMA/thread.
// ---------------------------------------------------------------------------
#define KT_PITCH 1040
#define OFF_KT   0
#define OFF_PE   (32*KT_PITCH*4)            // 133120
#define OFF_Q    (OFF_PE + 1056*16)          // 150016
#define OFF_P    (OFF_Q + 32*32*4)           // 154112
#define OFF_RED  (OFF_P + 32*4*4)            // 154624
#define OFF_MX   (OFF_RED + 32*16*4)         // 156672
#define OFF_INV  (OFF_MX + 32*4)             // 156800
#define OFF_MASK (OFF_INV + 32*4)            // 156928
#define SMEM_ATTN (OFF_MASK + 1024)          // 157952

__global__ __launch_bounds__(512, 1) void attn_kernel(
    const unsigned char* __restrict__ kpm, float* __restrict__ out)
{
    extern __shared__ char smraw[];
    float*  k_t    = (float*)(smraw + OFF_KT);      // [32][1040]
    float4* pe_s   = (float4*)(smraw + OFF_PE);     // [1056]
    float*  q_s    = (float*)(smraw + OFF_Q);       // [32][32]
    float*  p_s    = (float*)(smraw + OFF_P);       // [32][4]
    float*  red_s  = (float*)(smraw + OFF_RED);     // [32][16]
    float*  mx_s   = (float*)(smraw + OFF_MX);      // [32]
    float*  inv_s  = (float*)(smraw + OFF_INV);     // [32]
    unsigned char* mask_s = (unsigned char*)(smraw + OFF_MASK);

    const int tid = threadIdx.x;
    const int w = tid >> 5, lane = tid & 31;
    const int hb = blockIdx.y;
    const int h = hb >> 3, b = hb & 7;
    const int q0 = blockIdx.x * 32;

    // ---- fills ----
    if (tid < 256) {
        ((float4*)q_s)[tid] = ((const float4*)(g_q + ((size_t)hb*SQ + q0)*QHD))[tid];
        ((uchar4*)mask_s)[tid] = ((const uchar4*)(kpm + (size_t)b*SQ))[tid];
    }
    if (tid < 32) ((float4*)p_s)[tid] = ((const float4*)(g_p + ((size_t)hb*SQ + q0)*PHD))[tid];
    {
        const int nlo = 992 - q0;
        const float4* pesrc = &g_pe[h*NPOS + nlo];
        for (int i = tid; i < 1055; i += 512) pe_s[i] = pesrc[i];
    }
    {
        const float4* k4 = (const float4*)g_k + (size_t)hb*SQ*8;
#pragma unroll
        for (int i = 0; i < 16; ++i) {
            int idx = tid + i*512;
            int j = idx >> 3, d4 = idx & 7;
            float4 v = __ldg(&k4[idx]);
            k_t[(4*d4+0)*KT_PITCH + j] = v.x;
            k_t[(4*d4+1)*KT_PITCH + j] = v.y;
            k_t[(4*d4+2)*KT_PITCH + j] = v.z;
            k_t[(4*d4+3)*KT_PITCH + j] = v.w;
        }
    }
    __syncthreads();

    const int j0 = w*64 + lane;
    const int j1 = j0 + 32;

    float acc[32][2];
#pragma unroll
    for (int r = 0; r < 32; ++r) { acc[r][0] = 0.f; acc[r][1] = 0.f; }

    // ---- mainloop: K = 32 dims, 4 at a time ----
#pragma unroll 1
    for (int kk4 = 0; kk4 < 8; ++kk4) {
        const int kb = kk4 * 4;
        const float* kt0 = &k_t[(kb+0)*KT_PITCH];
        const float* kt1 = &k_t[(kb+1)*KT_PITCH];
        const float* kt2 = &k_t[(kb+2)*KT_PITCH];
        const float* kt3 = &k_t[(kb+3)*KT_PITCH];
        float ka0 = kt0[j0], ka1 = kt1[j0], ka2 = kt2[j0], ka3 = kt3[j0];
        float kb0 = kt0[j1], kb1 = kt1[j1], kb2 = kt2[j1], kb3 = kt3[j1];
#pragma unroll
        for (int r = 0; r < 32; ++r) {
            float4 q4 = *(const float4*)&q_s[r*32 + kb];   // broadcast load
            float s0 = acc[r][0], s1 = acc[r][1];
            s0 = fmaf(q4.x, ka0, s0); s1 = fmaf(q4.x, kb0, s1);
            s0 = fmaf(q4.y, ka1, s0); s1 = fmaf(q4.y, kb1, s1);
            s0 = fmaf(q4.z, ka2, s0); s1 = fmaf(q4.z, kb2, s1);
            s0 = fmaf(q4.w, ka3, s0); s1 = fmaf(q4.w, kb3, s1);
            acc[r][0] = s0; acc[r][1] = s1;
        }
    }

    // ---- epilogue: pos scores + mask + per-row max ----
    const bool m0v = mask_s[j0] != 0;
    const bool m1v = mask_s[j1] != 0;
#pragma unroll
    for (int r = 0; r < 32; ++r) {
        float4 p4 = *(const float4*)&p_s[r*4];             // broadcast
        float4 pa = pe_s[j0 + 31 - r];
        float4 pb = pe_s[j1 + 31 - r];
        float s0 = acc[r][0] + p4.x*pa.x + p4.y*pa.y + p4.z*pa.z + p4.w*pa.w;
        float s1 = acc[r][1] + p4.x*pb.x + p4.y*pb.y + p4.z*pb.z + p4.w*pb.w;
        if (m0v) s0 = -1000.0f;
        if (m1v) s1 = -1000.0f;
        acc[r][0] = s0; acc[r][1] = s1;
        float m = fmaxf(s0, s1);
#pragma unroll
        for (int o = 16; o; o >>= 1) m = fmaxf(m, __shfl_xor_sync(0xffffffffu, m, o));
        if (lane == 0) red_s[r*16 + w] = m;
    }
    __syncthreads();
    if (tid < 32) {
        float m = red_s[tid*16];
#pragma unroll
        for (int i = 1; i < 16; ++i) m = fmaxf(m, red_s[tid*16 + i]);
        mx_s[tid] = m;
    }
    __syncthreads();

    // ---- exp + per-row sum ----
#pragma unroll
    for (int r = 0; r < 32; ++r) {
        float mx = mx_s[r];
        float e0 = __expf(acc[r][0] - mx);
        float e1 = __expf(acc[r][1] - mx);
        acc[r][0] = e0; acc[r][1] = e1;
        float s = e0 + e1;
#pragma unroll
        for (int o = 16; o; o >>= 1) s += __shfl_xor_sync(0xffffffffu, s, o);
        if (lane == 0) red_s[r*16 + w] = s;
    }
    __syncthreads();
    if (tid < 32) {
        float s = red_s[tid*16];
#pragma unroll
        for (int i = 1; i < 16; ++i) s += red_s[tid*16 + i];
        inv_s[tid] = 1.0f / s;
    }
    __syncthreads();

    // ---- normalize + store (streaming) ----
    float* obase = out + ((size_t)hb*SQ + q0)*SQ;
#pragma unroll
    for (int r = 0; r < 32; ++r) {
        float inv = inv_s[r];
        float* op = obase + (size_t)r*SQ;
        __stcs(&op[j0], acc[r][0] * inv);
        __stcs(&op[j1], acc[r][1] * inv);
    }
}

// ---------------------------------------------------------------------------
extern "C" void kernel_launch(void* const* d_in, const int* in_sizes, int n_in,
                              void* d_out, int out_size)
{
    const float* x            = (const float*)d_in[0];          // (S,B,E)
    const float* pos_emb      = (const float*)d_in[1];          // (1,2S-1,PDIM)
    const unsigned char* kpm  = (const unsigned char*)d_in[2];  // (B,S) bool
    const float* in_proj_w    = (const float*)d_in[3];          // (544,512)
    const float* in_proj_b    = (const float*)d_in[4];          // (544,)
    const float* linear_pos_w = (const float*)d_in[5];          // (32,192)
    float* out = (float*)d_out;                                 // (H,B,S,S)

    static bool attr_set = false;
    if (!attr_set) {
        cudaFuncSetAttribute(attn_kernel,
                             cudaFuncAttributeMaxDynamicSharedMemorySize, SMEM_ATTN);
        attr_set = true;
    }

    dim3 g1(5, 64);                          // N tiles x M tiles
    proj_kernel<<<g1, 256>>>(x, in_proj_w, in_proj_b);

    pe_kernel<<<(NPOS*NH + 255)/256, 256>>>(pos_emb, linear_pos_w);

    dim3 g3(SQ/32, NH*NB);                   // 32 x 64
    attn_kernel<<<g3, 512, SMEM_ATTN>>>(kpm, out);
}

// round 5
// speedup vs baseline: 1.2009x; 1.2009x over previous
#include <cuda_runtime.h>
#include <cuda_fp16.h>

#define SQ 1024
#define NB 8
#define NE 512
#define NH 8
#define QHD 32
#define PHD 4
#define PDIM 192
#define NPOS (2*SQ-1)   // 2047
#define INPROJ 544

typedef unsigned long long u64;

#define F32X2_FMA(d, a, b, c) \
    asm("fma.rn.f32x2 %0, %1, %2, %3;" : "=l"(d) : "l"(a), "l"(b), "l"(c))
#define F32X2_PACK(out, lo, hi) \
    asm("mov.b64 %0, {%1, %2};" : "=l"(out) : "f"(lo), "f"(hi))
#define F32X2_UNPACK(lo, hi, in) \
    asm("mov.b64 {%0, %1}, %2;" : "=f"(lo), "=f"(hi) : "l"(in))

// Scratch (device globals; no allocations allowed)
__device__ __align__(16) float g_q[NH*NB*SQ*QHD];   // [h][b][s][d]
__device__ __align__(16) float g_k[NH*NB*SQ*QHD];   // [h][b][s][d]
__device__ __align__(16) float g_p[NH*NB*SQ*PHD];   // [h][b][s][d]
__device__ __align__(16) uint2 g_pe_h[NH*NPOS];     // [h][n]: 4 x fp16

// ---------------------------------------------------------------------------
// Kernel 1: proj = x @ W^T + b -> g_q/g_k/g_p.
// Tile 128Mx64Nx16K, 256 thr, 8x4 per thread as 4 row-pairs x 4 cols, FFMA2.
// Grid (9, 64) = 576 blocks, occ 3.
// ---------------------------------------------------------------------------
__global__ __launch_bounds__(256, 3) void proj_kernel(
    const float* __restrict__ x, const float* __restrict__ w,
    const float* __restrict__ bias)
{
    __shared__ float As[16][132];   // [k][row], pitch 132 (=4 mod 32: 2-way max)
    __shared__ float Bs[16][68];    // [k][col]
    const int tid = threadIdx.x;
    const int tx = tid & 15, ty = tid >> 4;   // tx: col group, ty: row group
    const int m0 = blockIdx.y * 128;
    const int n0 = blockIdx.x * 64;

    // fill mappings
    const int a_row = tid >> 1;               // 0..127
    const int a_kq  = tid & 1;                // 2 float4s per row per kt
    const int b_col = tid >> 2;               // 0..63
    const int b_kq  = tid & 3;
    const bool bvalid = (n0 + b_col) < INPROJ;
    const float4* xr = (const float4*)&x[(size_t)(m0 + a_row)*NE];
    const float4* wr = bvalid ? (const float4*)&w[(size_t)(n0 + b_col)*NE]
                              : (const float4*)w;

    u64 acc[4][4];
#pragma unroll
    for (int i = 0; i < 4; ++i)
#pragma unroll
        for (int j = 0; j < 4; ++j) acc[i][j] = 0ULL;

    for (int kt = 0; kt < 32; ++kt) {
        float4 av0 = xr[kt*4 + a_kq*2 + 0];
        float4 av1 = xr[kt*4 + a_kq*2 + 1];
        float4 bv  = make_float4(0.f,0.f,0.f,0.f);
        if (bvalid) bv = wr[kt*4 + b_kq];
        __syncthreads();
        {
            int k0 = a_kq*8;
            As[k0+0][a_row] = av0.x; As[k0+1][a_row] = av0.y;
            As[k0+2][a_row] = av0.z; As[k0+3][a_row] = av0.w;
            As[k0+4][a_row] = av1.x; As[k0+5][a_row] = av1.y;
            As[k0+6][a_row] = av1.z; As[k0+7][a_row] = av1.w;
            int k1 = b_kq*4;
            Bs[k1+0][b_col] = bv.x; Bs[k1+1][b_col] = bv.y;
            Bs[k1+2][b_col] = bv.z; Bs[k1+3][b_col] = bv.w;
        }
        __syncthreads();
#pragma unroll
        for (int k = 0; k < 16; ++k) {
            // a: rows ty*8..ty*8+7 -> 4 ready-made f32x2 row-pairs
            ulonglong2 au0 = *(const ulonglong2*)&As[k][ty*8];
            ulonglong2 au1 = *(const ulonglong2*)&As[k][ty*8 + 4];
            float4 bv4 = *(const float4*)&Bs[k][tx*4];
            u64 ap[4] = {au0.x, au0.y, au1.x, au1.y};
            u64 bp[4];
            F32X2_PACK(bp[0], bv4.x, bv4.x);
            F32X2_PACK(bp[1], bv4.y, bv4.y);
            F32X2_PACK(bp[2], bv4.z, bv4.z);
            F32X2_PACK(bp[3], bv4.w, bv4.w);
#pragma unroll
            for (int i = 0; i < 4; ++i)
#pragma unroll
                for (int j = 0; j < 4; ++j)
                    F32X2_FMA(acc[i][j], ap[i], bp[j], acc[i][j]);
        }
    }

    float bs[4];
#pragma unroll
    for (int j = 0; j < 4; ++j) {
        int n = n0 + tx*4 + j;
        bs[j] = (n < INPROJ) ? __ldg(&bias[n]) : 0.f;
    }
#pragma unroll
    for (int pr = 0; pr < 4; ++pr) {
#pragma unroll
        for (int j = 0; j < 4; ++j) {
            int n = n0 + tx*4 + j;
            if (n >= INPROJ) continue;
            float v0, v1;
            F32X2_UNPACK(v0, v1, acc[pr][j]);
            v0 += bs[j]; v1 += bs[j];
#pragma unroll
            for (int rr = 0; rr < 2; ++rr) {
                int m = m0 + ty*8 + pr*2 + rr;
                int s = m >> 3, b = m & 7;
                float v = rr ? v1 : v0;
                if (n < 256) {
                    int h = n >> 5, d = n & 31;
                    g_q[(((h<<3)+b)*SQ + s)*QHD + d] = v;
                } else if (n < 512) {
                    int n2 = n - 256; int h = n2 >> 5, d = n2 & 31;
                    g_k[(((h<<3)+b)*SQ + s)*QHD + d] = v;
                } else {
                    int n3 = n - 512; int h = n3 >> 2, d = n3 & 3;
                    g_p[(((h<<3)+b)*SQ + s)*PHD + d] = v;
                }
            }
        }
    }
}

// ---------------------------------------------------------------------------
// Kernel 2: g_pe_h[h][n] = fp16x4 of sum_p pos_emb[n][p] * linear_pos_w[h*4+d][p]
// ---------------------------------------------------------------------------
__global__ __launch_bounds__(256) void pe_kernel(
    const float* __restrict__ pos_emb, const float* __restrict__ lw)
{
    __shared__ float ws[32*193];
    const int tid = threadIdx.x;
    for (int i = tid; i < 32*PDIM; i += 256) {
        int o = i / PDIM, p = i % PDIM;
        ws[o*193 + p] = lw[i];
    }
    __syncthreads();
    int idx = blockIdx.x * 256 + tid;
    if (idx >= NPOS*NH) return;
    int n = idx >> 3, h = idx & 7;
    float a0 = 0.f, a1 = 0.f, a2 = 0.f, a3 = 0.f;
    const float* pr = &pos_emb[(size_t)n*PDIM];
#pragma unroll 4
    for (int p = 0; p < PDIM; ++p) {
        float pv = __ldg(&pr[p]);
        a0 = fmaf(pv, ws[(h*4+0)*193 + p], a0);
        a1 = fmaf(pv, ws[(h*4+1)*193 + p], a1);
        a2 = fmaf(pv, ws[(h*4+2)*193 + p], a2);
        a3 = fmaf(pv, ws[(h*4+3)*193 + p], a3);
    }
    __half2 h01 = __floats2half2_rn(a0, a1);
    __half2 h23 = __floats2half2_rn(a2, a3);
    g_pe_h[h*NPOS + n] = make_uint2(*(unsigned*)&h01, *(unsigned*)&h23);
}

// ---------------------------------------------------------------------------
// Kernel 3: fused scores + rel-shift + mask + softmax (no-max, exp-safe).
// Block: 32 q-rows x 1024 j, 512 thr. Thread owns j0=w*64+lane, j1=j0+32, all
// rows as 16 f32x2 row-pairs. k packed (k,k) per j; q pre-interleaved so one
// LDS.128 yields two (row,row+1) f32x2 operands for two dims.
// ---------------------------------------------------------------------------
#define KT_PITCH 1040
#define OFF_KT   0
#define OFF_PE   (32*KT_PITCH*4)             // 133120
#define OFF_Q    (OFF_PE + 1056*8)           // 141568
#define OFF_P    (OFF_Q + 16*16*16)          // 145664
#define OFF_RED  (OFF_P + 32*4*4)            // 146176
#define OFF_INV  (OFF_RED + 32*16*4)         // 148224
#define OFF_MASK (OFF_INV + 32*4)            // 148352
#define SMEM_ATTN (OFF_MASK + 1024)          // 149376

__global__ __launch_bounds__(512, 1) void attn_kernel(
    const unsigned char* __restrict__ kpm, float* __restrict__ out)
{
    extern __shared__ char smraw[];
    float*  k_t    = (float*)(smraw + OFF_KT);       // [32][1040]
    uint2*  pe_s   = (uint2*)(smraw + OFF_PE);       // [1056] fp16x4
    float4* q_s4   = (float4*)(smraw + OFF_Q);       // [16 rp][16 dp] interleaved
    float*  p_s    = (float*)(smraw + OFF_P);        // [32][4]
    float*  red_s  = (float*)(smraw + OFF_RED);      // [32][16]
    float*  inv_s  = (float*)(smraw + OFF_INV);      // [32]
    unsigned char* mask_s = (unsigned char*)(smraw + OFF_MASK);

    const int tid = threadIdx.x;
    const int w = tid >> 5, lane = tid & 31;
    const int hb = blockIdx.y;
    const int h = hb >> 3, b = hb & 7;
    const int q0 = blockIdx.x * 32;

    // ---- fills ----
    if (tid < 256) {
        // q interleaved: q_s4[rp*16+dp] = {qA[2dp], qB[2dp], qA[2dp+1], qB[2dp+1]}
        int rp = tid >> 4, dp = tid & 15;
        const float* gq = g_q + ((size_t)hb*SQ + q0)*QHD;
        float2 a = *(const float2*)&gq[(2*rp)*QHD + 2*dp];
        float2 c = *(const float2*)&gq[(2*rp+1)*QHD + 2*dp];
        q_s4[tid] = make_float4(a.x, c.x, a.y, c.y);
        ((uchar4*)mask_s)[tid] = ((const uchar4*)(kpm + (size_t)b*SQ))[tid];
    }
    if (tid < 32) ((float4*)p_s)[tid] = ((const float4*)(g_p + ((size_t)hb*SQ + q0)*PHD))[tid];
    {
        const int nlo = 992 - q0;
        const uint2* pesrc = &g_pe_h[h*NPOS + nlo];
        for (int i = tid; i < 1055; i += 512) pe_s[i] = pesrc[i];
    }
    {   // k_t fill: d4-outer so lanes store consecutive j -> conflict-free STS
        const float4* k4 = (const float4*)g_k + (size_t)hb*SQ*8;
#pragma unroll
        for (int d4 = 0; d4 < 8; ++d4) {
#pragma unroll
            for (int hf = 0; hf < 2; ++hf) {
                int j = hf*512 + tid;
                float4 v = __ldg(&k4[(size_t)j*8 + d4]);
                k_t[(4*d4+0)*KT_PITCH + j] = v.x;
                k_t[(4*d4+1)*KT_PITCH + j] = v.y;
                k_t[(4*d4+2)*KT_PITCH + j] = v.z;
                k_t[(4*d4+3)*KT_PITCH + j] = v.w;
            }
        }
    }
    __syncthreads();

    const int j0 = w*64 + lane;
    const int j1 = j0 + 32;
    const ulonglong2* qs2 = (const ulonglong2*)q_s4;

    u64 accA[16], accB[16];
#pragma unroll
    for (int i = 0; i < 16; ++i) { accA[i] = 0ULL; accB[i] = 0ULL; }

    // ---- mainloop: 32 dims, 4 at a time ----
#pragma unroll 1
    for (int kk4 = 0; kk4 < 8; ++kk4) {
        const int kb = kk4 * 4;
        float k0a = k_t[(kb+0)*KT_PITCH + j0];
        float k1a = k_t[(kb+1)*KT_PITCH + j0];
        float k2a = k_t[(kb+2)*KT_PITCH + j0];
        float k3a = k_t[(kb+3)*KT_PITCH + j0];
        float k0b = k_t[(kb+0)*KT_PITCH + j1];
        float k1b = k_t[(kb+1)*KT_PITCH + j1];
        float k2b = k_t[(kb+2)*KT_PITCH + j1];
        float k3b = k_t[(kb+3)*KT_PITCH + j1];
        u64 kp0a, kp1a, kp2a, kp3a, kp0b, kp1b, kp2b, kp3b;
        F32X2_PACK(kp0a, k0a, k0a); F32X2_PACK(kp1a, k1a, k1a);
        F32X2_PACK(kp2a, k2a, k2a); F32X2_PACK(kp3a, k3a, k3a);
        F32X2_PACK(kp0b, k0b, k0b); F32X2_PACK(kp1b, k1b, k1b);
        F32X2_PACK(kp2b, k2b, k2b); F32X2_PACK(kp3b, k3b, k3b);
        const int dpb = kb >> 1;
#pragma unroll
        for (int rp = 0; rp < 16; ++rp) {
            ulonglong2 qu0 = qs2[rp*16 + dpb];      // pairs for dims kb, kb+1
            ulonglong2 qu1 = qs2[rp*16 + dpb + 1];  // pairs for dims kb+2, kb+3
            F32X2_FMA(accA[rp], qu0.x, kp0a, accA[rp]);
            F32X2_FMA(accB[rp], qu0.x, kp0b, accB[rp]);
            F32X2_FMA(accA[rp], qu0.y, kp1a, accA[rp]);
            F32X2_FMA(accB[rp], qu0.y, kp1b, accB[rp]);
            F32X2_FMA(accA[rp], qu1.x, kp2a, accA[rp]);
            F32X2_FMA(accB[rp], qu1.x, kp2b, accB[rp]);
            F32X2_FMA(accA[rp], qu1.y, kp3a, accA[rp]);
            F32X2_FMA(accB[rp], qu1.y, kp3b, accB[rp]);
        }
    }

    // ---- epilogue: pos (fp16 pe) + mask + exp (no max pass) + row sums ----
    const bool m0v = mask_s[j0] != 0;
    const bool m1v = mask_s[j1] != 0;
#pragma unroll
    for (int rp = 0; rp < 16; ++rp) {
        float sA0, sA1, sB0, sB1;
        F32X2_UNPACK(sA0, sA1, accA[rp]);
        F32X2_UNPACK(sB0, sB1, accB[rp]);
        float e0[2], e1[2];
#pragma unroll
        for (int rr = 0; rr < 2; ++rr) {
            int r = 2*rp + rr;
            float sa = rr ? sA1 : sA0;
            float sb = rr ? sB1 : sB0;
            float4 p4 = *(const float4*)&p_s[r*4];          // broadcast
            uint2 pea = pe_s[j0 + 31 - r];
            uint2 peb = pe_s[j1 + 31 - r];
            float2 fa01 = __half22float2(*(__half2*)&pea.x);
            float2 fa23 = __half22float2(*(__half2*)&pea.y);
            float2 fb01 = __half22float2(*(__half2*)&peb.x);
            float2 fb23 = __half22float2(*(__half2*)&peb.y);
            sa += p4.x*fa01.x + p4.y*fa01.y + p4.z*fa23.x + p4.w*fa23.y;
            sb += p4.x*fb01.x + p4.y*fb01.y + p4.z*fb23.x + p4.w*fb23.y;
            float ea = m0v ? 0.f : __expf(sa);
            float eb = m1v ? 0.f : __expf(sb);
            e0[rr] = ea; e1[rr] = eb;
            float s = ea + eb;
#pragma unroll
            for (int o = 16; o; o >>= 1) s += __shfl_xor_sync(0xffffffffu, s, o);
            if (lane == 0) red_s[r*16 + w] = s;
        }
        F32X2_PACK(accA[rp], e0[0], e0[1]);
        F32X2_PACK(accB[rp], e1[0], e1[1]);
    }
    __syncthreads();
    if (tid < 32) {
        float s = red_s[tid*16];
#pragma unroll
        for (int i = 1; i < 16; ++i) s += red_s[tid*16 + i];
        inv_s[tid] = 1.0f / s;
    }
    __syncthreads();

    // ---- normalize + streaming store ----
    float* obase = out + ((size_t)hb*SQ + q0)*SQ;
#pragma unroll
    for (int rp = 0; rp < 16; ++rp) {
        float eA0, eA1, eB0, eB1;
        F32X2_UNPACK(eA0, eA1, accA[rp]);
        F32X2_UNPACK(eB0, eB1, accB[rp]);
        float i0 = inv_s[2*rp], i1 = inv_s[2*rp+1];
        float* op0 = obase + (size_t)(2*rp)*SQ;
        float* op1 = obase + (size_t)(2*rp+1)*SQ;
        __stcs(&op0[j0], eA0 * i0);
        __stcs(&op0[j1], eB0 * i0);
        __stcs(&op1[j0], eA1 * i1);
        __stcs(&op1[j1], eB1 * i1);
    }
}

// ---------------------------------------------------------------------------
extern "C" void kernel_launch(void* const* d_in, const int* in_sizes, int n_in,
                              void* d_out, int out_size)
{
    const float* x            = (const float*)d_in[0];          // (S,B,E)
    const float* pos_emb      = (const float*)d_in[1];          // (1,2S-1,PDIM)
    const unsigned char* kpm  = (const unsigned char*)d_in[2];  // (B,S) bool
    const float* in_proj_w    = (const float*)d_in[3];          // (544,512)
    const float* in_proj_b    = (const float*)d_in[4];          // (544,)
    const float* linear_pos_w = (const float*)d_in[5];          // (32,192)
    float* out = (float*)d_out;                                 // (H,B,S,S)

    static bool attr_set = false;
    if (!attr_set) {
        cudaFuncSetAttribute(attn_kernel,
                             cudaFuncAttributeMaxDynamicSharedMemorySize, SMEM_ATTN);
        attr_set = true;
    }

    dim3 g1(9, 64);                          // N tiles (64) x M tiles (128)
    proj_kernel<<<g1, 256>>>(x, in_proj_w, in_proj_b);

    pe_kernel<<<(NPOS*NH + 255)/256, 256>>>(pos_emb, linear_pos_w);

    dim3 g3(SQ/32, NH*NB);                   // 32 x 64
    attn_kernel<<<g3, 512, SMEM_ATTN>>>(kpm, out);
}

// round 6
// speedup vs baseline: 1.4135x; 1.1771x over previous
#include <cuda_runtime.h>
#include <cuda_fp16.h>

#define SQ 1024
#define NB 8
#define NE 512
#define NH 8
#define QHD 32
#define PHD 4
#define PDIM 192
#define NPOS (2*SQ-1)   // 2047
#define INPROJ 544

typedef unsigned long long u64;

#define F32X2_FMA(d, a, b, c) \
    asm("fma.rn.f32x2 %0, %1, %2, %3;" : "=l"(d) : "l"(a), "l"(b), "l"(c))
#define F32X2_PACK(out, lo, hi) \
    asm("mov.b64 %0, {%1, %2};" : "=l"(out) : "f"(lo), "f"(hi))
#define F32X2_UNPACK(lo, hi, in) \
    asm("mov.b64 {%0, %1}, %2;" : "=f"(lo), "=f"(hi) : "l"(in))

// Scratch (device globals; no allocations allowed)
__device__ __align__(16) float g_q[NH*NB*SQ*QHD];   // [h][b][s][d]
__device__ __align__(16) float g_k[NH*NB*SQ*QHD];   // [h][b][s][d]
__device__ __align__(16) float g_p[NH*NB*SQ*PHD];   // [h][b][s][d]
__device__ __align__(16) uint2 g_pe_h[NH*NPOS];     // [h][n]: 4 x fp16

// ---------------------------------------------------------------------------
// Kernel 1: proj = x @ W^T + b -> g_q/g_k/g_p.
// Tile 256Mx64Nx16K, 256 thr. Thread: 4 row-pairs (8 rows) x 8 cols, FFMA2.
// Double-buffered smem, one __syncthreads per k-tile.
// Grid (9, 32) = 288 blocks = exactly one wave at occupancy 2.
// ---------------------------------------------------------------------------
#define AP 260   // As pitch (mult of 4 for 16B loads; 2-way STS conflict max)
#define BP 68

__global__ __launch_bounds__(256, 2) void proj_kernel(
    const float* __restrict__ x, const float* __restrict__ w,
    const float* __restrict__ bias)
{
    __shared__ float As[2][16][AP];
    __shared__ float Bs[2][16][BP];
    const int tid = threadIdx.x;
    const int tx = tid & 7;          // col group: cols tx*8..tx*8+7
    const int ty = tid >> 3;         // row group: rows ty*8..ty*8+7
    const int m0 = blockIdx.y * 256;
    const int n0 = blockIdx.x * 64;

    const float4* x4 = (const float4*)x;
    const float4* w4 = (const float4*)w;

    // fill mappings
    const int bcol = tid >> 2, bkq = tid & 3;
    const bool bvalid = (n0 + bcol) < INPROJ;

    float4 av[4], bv;
    // prefetch kt = 0
#pragma unroll
    for (int t = 0; t < 4; ++t) {
        int idx = tid + t*256;
        int arow = idx >> 2, akq = idx & 3;
        av[t] = __ldg(&x4[(size_t)(m0 + arow)*128 + akq]);
    }
    bv = bvalid ? __ldg(&w4[(size_t)(n0 + bcol)*128 + bkq])
                : make_float4(0.f,0.f,0.f,0.f);

    u64 acc[4][8];
#pragma unroll
    for (int i = 0; i < 4; ++i)
#pragma unroll
        for (int j = 0; j < 8; ++j) acc[i][j] = 0ULL;

    for (int kt = 0; kt < 32; ++kt) {
        const int s = kt & 1;
        // store current regs
#pragma unroll
        for (int t = 0; t < 4; ++t) {
            int idx = tid + t*256;
            int arow = idx >> 2, akq = idx & 3;
            As[s][4*akq+0][arow] = av[t].x;
            As[s][4*akq+1][arow] = av[t].y;
            As[s][4*akq+2][arow] = av[t].z;
            As[s][4*akq+3][arow] = av[t].w;
        }
        Bs[s][4*bkq+0][bcol] = bv.x;
        Bs[s][4*bkq+1][bcol] = bv.y;
        Bs[s][4*bkq+2][bcol] = bv.z;
        Bs[s][4*bkq+3][bcol] = bv.w;
        __syncthreads();
        // prefetch next k-tile (overlaps compute below)
        if (kt < 31) {
#pragma unroll
            for (int t = 0; t < 4; ++t) {
                int idx = tid + t*256;
                int arow = idx >> 2, akq = idx & 3;
                av[t] = __ldg(&x4[(size_t)(m0 + arow)*128 + (kt+1)*4 + akq]);
            }
            if (bvalid) bv = __ldg(&w4[(size_t)(n0 + bcol)*128 + (kt+1)*4 + bkq]);
        }
#pragma unroll
        for (int k = 0; k < 16; ++k) {
            ulonglong2 au0 = *(const ulonglong2*)&As[s][k][ty*8];
            ulonglong2 au1 = *(const ulonglong2*)&As[s][k][ty*8 + 4];
            float4 b0 = *(const float4*)&Bs[s][k][tx*8];
            float4 b1 = *(const float4*)&Bs[s][k][tx*8 + 4];
            u64 ap[4] = {au0.x, au0.y, au1.x, au1.y};
            u64 bp[8];
            F32X2_PACK(bp[0], b0.x, b0.x); F32X2_PACK(bp[1], b0.y, b0.y);
            F32X2_PACK(bp[2], b0.z, b0.z); F32X2_PACK(bp[3], b0.w, b0.w);
            F32X2_PACK(bp[4], b1.x, b1.x); F32X2_PACK(bp[5], b1.y, b1.y);
            F32X2_PACK(bp[6], b1.z, b1.z); F32X2_PACK(bp[7], b1.w, b1.w);
#pragma unroll
            for (int i = 0; i < 4; ++i)
#pragma unroll
                for (int j = 0; j < 8; ++j)
                    F32X2_FMA(acc[i][j], ap[i], bp[j], acc[i][j]);
        }
    }

    float bs[8];
#pragma unroll
    for (int j = 0; j < 8; ++j) {
        int n = n0 + tx*8 + j;
        bs[j] = (n < INPROJ) ? __ldg(&bias[n]) : 0.f;
    }
#pragma unroll
    for (int pr = 0; pr < 4; ++pr) {
#pragma unroll
        for (int j = 0; j < 8; ++j) {
            int n = n0 + tx*8 + j;
            if (n >= INPROJ) continue;
            float v0, v1;
            F32X2_UNPACK(v0, v1, acc[pr][j]);
            v0 += bs[j]; v1 += bs[j];
#pragma unroll
            for (int rr = 0; rr < 2; ++rr) {
                int m = m0 + ty*8 + pr*2 + rr;
                int s = m >> 3, b = m & 7;
                float v = rr ? v1 : v0;
                if (n < 256) {
                    int h = n >> 5, d = n & 31;
                    g_q[(((h<<3)+b)*SQ + s)*QHD + d] = v;
                } else if (n < 512) {
                    int n2 = n - 256; int h = n2 >> 5, d = n2 & 31;
                    g_k[(((h<<3)+b)*SQ + s)*QHD + d] = v;
                } else {
                    int n3 = n - 512; int h = n3 >> 2, d = n3 & 3;
                    g_p[(((h<<3)+b)*SQ + s)*PHD + d] = v;
                }
            }
        }
    }
}

// ---------------------------------------------------------------------------
// Kernel 2: g_pe_h[h][n] = fp16x4 of sum_p pos_emb[n][p] * lw[h*4+d][p]
// Grid (8 n-blocks, 8 h): h uniform per block -> all weight LDS are broadcast.
// ---------------------------------------------------------------------------
__global__ __launch_bounds__(256) void pe_kernel(
    const float* __restrict__ pos_emb, const float* __restrict__ lw)
{
    __shared__ float ws[4][193];
    const int tid = threadIdx.x;
    const int h = blockIdx.y;
    for (int i = tid; i < 4*PDIM; i += 256) {
        int o = i / PDIM, p = i % PDIM;
        ws[o][p] = lw[(h*4+o)*PDIM + p];
    }
    __syncthreads();
    int n = blockIdx.x * 256 + tid;
    if (n >= NPOS) return;
    float a0 = 0.f, a1 = 0.f, a2 = 0.f, a3 = 0.f;
    const float4* pr = (const float4*)&pos_emb[(size_t)n*PDIM];
#pragma unroll 4
    for (int p4 = 0; p4 < PDIM/4; ++p4) {
        float4 pv = __ldg(&pr[p4]);
        int p = p4*4;
        a0 = fmaf(pv.x, ws[0][p+0], a0); a1 = fmaf(pv.x, ws[1][p+0], a1);
        a2 = fmaf(pv.x, ws[2][p+0], a2); a3 = fmaf(pv.x, ws[3][p+0], a3);
        a0 = fmaf(pv.y, ws[0][p+1], a0); a1 = fmaf(pv.y, ws[1][p+1], a1);
        a2 = fmaf(pv.y, ws[2][p+1], a2); a3 = fmaf(pv.y, ws[3][p+1], a3);
        a0 = fmaf(pv.z, ws[0][p+2], a0); a1 = fmaf(pv.z, ws[1][p+2], a1);
        a2 = fmaf(pv.z, ws[2][p+2], a2); a3 = fmaf(pv.z, ws[3][p+2], a3);
        a0 = fmaf(pv.w, ws[0][p+3], a0); a1 = fmaf(pv.w, ws[1][p+3], a1);
        a2 = fmaf(pv.w, ws[2][p+3], a2); a3 = fmaf(pv.w, ws[3][p+3], a3);
    }
    __half2 h01 = __floats2half2_rn(a0, a1);
    __half2 h23 = __floats2half2_rn(a2, a3);
    g_pe_h[h*NPOS + n] = make_uint2(*(unsigned*)&h01, *(unsigned*)&h23);
}

// ---------------------------------------------------------------------------
// Kernel 3: fused scores + rel-shift + mask + softmax (no-max, exp-safe).
// 512 thr, 32 q-rows x 1024 j. Coalesced k fill + conflict-free transposed
// STS (pitch 1041 == 17 mod 32). FFMA2 mainloop with k-register prefetch.
// ---------------------------------------------------------------------------
#define KT_PITCH 1041
#define OFF_KT   0
#define OFF_PE   (32*KT_PITCH*4)             // 133248
#define OFF_Q    (OFF_PE + 1056*8)           // 141696
#define OFF_P    (OFF_Q + 16*16*16)          // 145792
#define OFF_RED  (OFF_P + 32*4*4)            // 146304
#define OFF_INV  (OFF_RED + 32*16*4)         // 148352
#define OFF_MASK (OFF_INV + 32*4)            // 148480
#define SMEM_ATTN (OFF_MASK + 1024)          // 149504

__global__ __launch_bounds__(512, 1) void attn_kernel(
    const unsigned char* __restrict__ kpm, float* __restrict__ out)
{
    extern __shared__ char smraw[];
    float*  k_t    = (float*)(smraw + OFF_KT);       // [32][1041]
    uint2*  pe_s   = (uint2*)(smraw + OFF_PE);       // [1056] fp16x4
    float4* q_s4   = (float4*)(smraw + OFF_Q);       // [16 rp][16 dp] interleaved
    float*  p_s    = (float*)(smraw + OFF_P);        // [32][4]
    float*  red_s  = (float*)(smraw + OFF_RED);      // [32][16]
    float*  inv_s  = (float*)(smraw + OFF_INV);      // [32]
    unsigned char* mask_s = (unsigned char*)(smraw + OFF_MASK);

    const int tid = threadIdx.x;
    const int w = tid >> 5, lane = tid & 31;
    const int hb = blockIdx.y;
    const int h = hb >> 3, b = hb & 7;
    const int q0 = blockIdx.x * 32;

    // ---- fills ----
    if (tid < 256) {
        // q interleaved: q_s4[rp*16+dp] = {qA[2dp], qB[2dp], qA[2dp+1], qB[2dp+1]}
        int rp = tid >> 4, dp = tid & 15;
        const float* gq = g_q + ((size_t)hb*SQ + q0)*QHD;
        float2 a = *(const float2*)&gq[(2*rp)*QHD + 2*dp];
        float2 c = *(const float2*)&gq[(2*rp+1)*QHD + 2*dp];
        q_s4[tid] = make_float4(a.x, c.x, a.y, c.y);
        ((uchar4*)mask_s)[tid] = ((const uchar4*)(kpm + (size_t)b*SQ))[tid];
    }
    if (tid < 32) ((float4*)p_s)[tid] = ((const float4*)(g_p + ((size_t)hb*SQ + q0)*PHD))[tid];
    {
        const int nlo = 992 - q0;
        const uint2* pesrc = &g_pe_h[h*NPOS + nlo];
        for (int i = tid; i < 1055; i += 512) pe_s[i] = pesrc[i];
    }
    {   // coalesced LDG; STS conflict-free via pitch 1041 (==17 mod 32)
        const float4* k4 = (const float4*)g_k + (size_t)hb*SQ*8;
#pragma unroll
        for (int i = 0; i < 16; ++i) {
            int idx = tid + i*512;
            int j = idx >> 3, d4 = idx & 7;
            float4 v = __ldg(&k4[idx]);
            k_t[(4*d4+0)*KT_PITCH + j] = v.x;
            k_t[(4*d4+1)*KT_PITCH + j] = v.y;
            k_t[(4*d4+2)*KT_PITCH + j] = v.z;
            k_t[(4*d4+3)*KT_PITCH + j] = v.w;
        }
    }
    __syncthreads();

    const int j0 = w*64 + lane;
    const int j1 = j0 + 32;
    const ulonglong2* qs2 = (const ulonglong2*)q_s4;

    u64 accA[16], accB[16];
#pragma unroll
    for (int i = 0; i < 16; ++i) { accA[i] = 0ULL; accB[i] = 0ULL; }

    // ---- mainloop: 32 dims, 4 at a time, k-reg prefetch ----
    float kr[8], kn[8];
#pragma unroll
    for (int d = 0; d < 4; ++d) {
        kr[d]   = k_t[d*KT_PITCH + j0];
        kr[4+d] = k_t[d*KT_PITCH + j1];
    }
#pragma unroll
    for (int kk4 = 0; kk4 < 8; ++kk4) {
        const int kb = kk4 * 4;
        if (kk4 < 7) {
#pragma unroll
            for (int d = 0; d < 4; ++d) {
                kn[d]   = k_t[(kb+4+d)*KT_PITCH + j0];
                kn[4+d] = k_t[(kb+4+d)*KT_PITCH + j1];
            }
        }
        u64 kpA[4], kpB[4];
        F32X2_PACK(kpA[0], kr[0], kr[0]); F32X2_PACK(kpA[1], kr[1], kr[1]);
        F32X2_PACK(kpA[2], kr[2], kr[2]); F32X2_PACK(kpA[3], kr[3], kr[3]);
        F32X2_PACK(kpB[0], kr[4], kr[4]); F32X2_PACK(kpB[1], kr[5], kr[5]);
        F32X2_PACK(kpB[2], kr[6], kr[6]); F32X2_PACK(kpB[3], kr[7], kr[7]);
        const int dpb = kb >> 1;
#pragma unroll
        for (int rp = 0; rp < 16; ++rp) {
            ulonglong2 qu0 = qs2[rp*16 + dpb];      // pairs for dims kb, kb+1
            ulonglong2 qu1 = qs2[rp*16 + dpb + 1];  // pairs for dims kb+2, kb+3
            F32X2_FMA(accA[rp], qu0.x, kpA[0], accA[rp]);
            F32X2_FMA(accB[rp], qu0.x, kpB[0], accB[rp]);
            F32X2_FMA(accA[rp], qu0.y, kpA[1], accA[rp]);
            F32X2_FMA(accB[rp], qu0.y, kpB[1], accB[rp]);
            F32X2_FMA(accA[rp], qu1.x, kpA[2], accA[rp]);
            F32X2_FMA(accB[rp], qu1.x, kpB[2], accB[rp]);
            F32X2_FMA(accA[rp], qu1.y, kpA[3], accA[rp]);
            F32X2_FMA(accB[rp], qu1.y, kpB[3], accB[rp]);
        }
#pragma unroll
        for (int d = 0; d < 8; ++d) kr[d] = kn[d];
    }

    // ---- epilogue: pos (fp16 pe) + mask + exp (no max pass) + row sums ----
    const bool m0v = mask_s[j0] != 0;
    const bool m1v = mask_s[j1] != 0;
#pragma unroll
    for (int rp = 0; rp < 16; ++rp) {
        float sA0, sA1, sB0, sB1;
        F32X2_UNPACK(sA0, sA1, accA[rp]);
        F32X2_UNPACK(sB0, sB1, accB[rp]);
        float e0[2], e1[2];
#pragma unroll
        for (int rr = 0; rr < 2; ++rr) {
            int r = 2*rp + rr;
            float sa = rr ? sA1 : sA0;
            float sb = rr ? sB1 : sB0;
            float4 p4 = *(const float4*)&p_s[r*4];          // broadcast
            uint2 pea = pe_s[j0 + 31 - r];
            uint2 peb = pe_s[j1 + 31 - r];
            float2 fa01 = __half22float2(*(__half2*)&pea.x);
            float2 fa23 = __half22float2(*(__half2*)&pea.y);
            float2 fb01 = __half22float2(*(__half2*)&peb.x);
            float2 fb23 = __half22float2(*(__half2*)&peb.y);
            sa += p4.x*fa01.x + p4.y*fa01.y + p4.z*fa23.x + p4.w*fa23.y;
            sb += p4.x*fb01.x + p4.y*fb01.y + p4.z*fb23.x + p4.w*fb23.y;
            float ea = m0v ? 0.f : __expf(sa);
            float eb = m1v ? 0.f : __expf(sb);
            e0[rr] = ea; e1[rr] = eb;
            float s = ea + eb;
#pragma unroll
            for (int o = 16; o; o >>= 1) s += __shfl_xor_sync(0xffffffffu, s, o);
            if (lane == 0) red_s[r*16 + w] = s;
        }
        F32X2_PACK(accA[rp], e0[0], e0[1]);
        F32X2_PACK(accB[rp], e1[0], e1[1]);
    }
    __syncthreads();
    if (tid < 32) {
        float s = red_s[tid*16];
#pragma unroll
        for (int i = 1; i < 16; ++i) s += red_s[tid*16 + i];
        inv_s[tid] = 1.0f / s;
    }
    __syncthreads();

    // ---- normalize + streaming store ----
    float* obase = out + ((size_t)hb*SQ + q0)*SQ;
#pragma unroll
    for (int rp = 0; rp < 16; ++rp) {
        float eA0, eA1, eB0, eB1;
        F32X2_UNPACK(eA0, eA1, accA[rp]);
        F32X2_UNPACK(eB0, eB1, accB[rp]);
        float i0 = inv_s[2*rp], i1 = inv_s[2*rp+1];
        float* op0 = obase + (size_t)(2*rp)*SQ;
        float* op1 = obase + (size_t)(2*rp+1)*SQ;
        __stcs(&op0[j0], eA0 * i0);
        __stcs(&op0[j1], eB0 * i0);
        __stcs(&op1[j0], eA1 * i1);
        __stcs(&op1[j1], eB1 * i1);
    }
}

// ---------------------------------------------------------------------------
extern "C" void kernel_launch(void* const* d_in, const int* in_sizes, int n_in,
                              void* d_out, int out_size)
{
    const float* x            = (const float*)d_in[0];          // (S,B,E)
    const float* pos_emb      = (const float*)d_in[1];          // (1,2S-1,PDIM)
    const unsigned char* kpm  = (const unsigned char*)d_in[2];  // (B,S) bool
    const float* in_proj_w    = (const float*)d_in[3];          // (544,512)
    const float* in_proj_b    = (const float*)d_in[4];          // (544,)
    const float* linear_pos_w = (const float*)d_in[5];          // (32,192)
    float* out = (float*)d_out;                                 // (H,B,S,S)

    static bool attr_set = false;
    if (!attr_set) {
        cudaFuncSetAttribute(attn_kernel,
                             cudaFuncAttributeMaxDynamicSharedMemorySize, SMEM_ATTN);
        attr_set = true;
    }

    dim3 g1(9, 32);                          // 288 blocks = 1 wave @ occ 2
    proj_kernel<<<g1, 256>>>(x, in_proj_w, in_proj_b);

    dim3 g2((NPOS + 255)/256, NH);           // 8 x 8
    pe_kernel<<<g2, 256>>>(pos_emb, linear_pos_w);

    dim3 g3(SQ/32, NH*NB);                   // 32 x 64
    attn_kernel<<<g3, 512, SMEM_ATTN>>>(kpm, out);
}

// round 7
// speedup vs baseline: 1.5848x; 1.1212x over previous
#include <cuda_runtime.h>
#include <cuda_fp16.h>
#include <cuda_bf16.h>

#define SQ 1024
#define NB 8
#define NE 512
#define NH 8
#define QHD 32
#define PHD 4
#define PDIM 192
#define NPOS (2*SQ-1)   // 2047
#define INPROJ 544

typedef unsigned long long u64;
typedef unsigned int u32;

#define F32X2_FMA(d, a, b, c) \
    asm("fma.rn.f32x2 %0, %1, %2, %3;" : "=l"(d) : "l"(a), "l"(b), "l"(c))
#define F32X2_PACK(out, lo, hi) \
    asm("mov.b64 %0, {%1, %2};" : "=l"(out) : "f"(lo), "f"(hi))
#define F32X2_UNPACK(lo, hi, in) \
    asm("mov.b64 {%0, %1}, %2;" : "=f"(lo), "=f"(hi) : "l"(in))

// bf16 mma m16n8k16, fp32 accumulate (in-place)
#define MMA16816(d, a0, a1, a2, a3, b0, b1) \
    asm("mma.sync.aligned.m16n8k16.row.col.f32.bf16.bf16.f32 " \
        "{%0,%1,%2,%3}, {%4,%5,%6,%7}, {%8,%9}, {%0,%1,%2,%3};" \
        : "+f"(d[0]), "+f"(d[1]), "+f"(d[2]), "+f"(d[3]) \
        : "r"(a0), "r"(a1), "r"(a2), "r"(a3), "r"(b0), "r"(b1))

// Scratch (device globals; no allocations allowed)
__device__ __align__(16) u32  g_qh[NH*NB*SQ*16];   // [hb][s][d2] bf16x2 hi
__device__ __align__(16) u32  g_ql[NH*NB*SQ*16];   // bf16x2 lo (residual)
__device__ __align__(16) u32  g_kh[NH*NB*SQ*16];
__device__ __align__(16) u32  g_kl[NH*NB*SQ*16];
__device__ __align__(16) float g_p[NH*NB*SQ*PHD];  // [hb][s][d] fp32
__device__ __align__(16) uint2 g_pe_h[NH*NPOS];    // [h][n]: 4 x fp16

// v0,v1 -> hi (bf16x2: lo-half=v0), lo = residual pair
__device__ __forceinline__ void split_pair(float c0, float c1, u32& hi, u32& lo)
{
    u32 h;
    asm("cvt.rn.bf16x2.f32 %0, %1, %2;" : "=r"(h) : "f"(c1), "f"(c0));
    float f0 = __uint_as_float(h << 16);
    float f1 = __uint_as_float(h & 0xffff0000u);
    float r0 = c0 - f0, r1 = c1 - f1;
    asm("cvt.rn.bf16x2.f32 %0, %1, %2;" : "=r"(lo) : "f"(r1), "f"(r0));
    hi = h;
}

// ---------------------------------------------------------------------------
// Kernel 1: proj = x @ W^T + b. FFMA2 GEMM (as R6); epilogue splits q/k into
// bf16 hi/lo pair arrays for the tensor-core attention kernel.
// ---------------------------------------------------------------------------
#define AP 260
#define BP 68

__global__ __launch_bounds__(256, 2) void proj_kernel(
    const float* __restrict__ x, const float* __restrict__ w,
    const float* __restrict__ bias)
{
    __shared__ float As[2][16][AP];
    __shared__ float Bs[2][16][BP];
    const int tid = threadIdx.x;
    const int tx = tid & 7;
    const int ty = tid >> 3;
    const int m0 = blockIdx.y * 256;
    const int n0 = blockIdx.x * 64;

    const float4* x4 = (const float4*)x;
    const float4* w4 = (const float4*)w;

    const int bcol = tid >> 2, bkq = tid & 3;
    const bool bvalid = (n0 + bcol) < INPROJ;

    float4 av[4], bv;
#pragma unroll
    for (int t = 0; t < 4; ++t) {
        int idx = tid + t*256;
        int arow = idx >> 2, akq = idx & 3;
        av[t] = __ldg(&x4[(size_t)(m0 + arow)*128 + akq]);
    }
    bv = bvalid ? __ldg(&w4[(size_t)(n0 + bcol)*128 + bkq])
                : make_float4(0.f,0.f,0.f,0.f);

    u64 acc[4][8];
#pragma unroll
    for (int i = 0; i < 4; ++i)
#pragma unroll
        for (int j = 0; j < 8; ++j) acc[i][j] = 0ULL;

    for (int kt = 0; kt < 32; ++kt) {
        const int s = kt & 1;
#pragma unroll
        for (int t = 0; t < 4; ++t) {
            int idx = tid + t*256;
            int arow = idx >> 2, akq = idx & 3;
            As[s][4*akq+0][arow] = av[t].x;
            As[s][4*akq+1][arow] = av[t].y;
            As[s][4*akq+2][arow] = av[t].z;
            As[s][4*akq+3][arow] = av[t].w;
        }
        Bs[s][4*bkq+0][bcol] = bv.x;
        Bs[s][4*bkq+1][bcol] = bv.y;
        Bs[s][4*bkq+2][bcol] = bv.z;
        Bs[s][4*bkq+3][bcol] = bv.w;
        __syncthreads();
        if (kt < 31) {
#pragma unroll
            for (int t = 0; t < 4; ++t) {
                int idx = tid + t*256;
                int arow = idx >> 2, akq = idx & 3;
                av[t] = __ldg(&x4[(size_t)(m0 + arow)*128 + (kt+1)*4 + akq]);
            }
            if (bvalid) bv = __ldg(&w4[(size_t)(n0 + bcol)*128 + (kt+1)*4 + bkq]);
        }
#pragma unroll
        for (int k = 0; k < 16; ++k) {
            ulonglong2 au0 = *(const ulonglong2*)&As[s][k][ty*8];
            ulonglong2 au1 = *(const ulonglong2*)&As[s][k][ty*8 + 4];
            float4 b0 = *(const float4*)&Bs[s][k][tx*8];
            float4 b1 = *(const float4*)&Bs[s][k][tx*8 + 4];
            u64 ap[4] = {au0.x, au0.y, au1.x, au1.y};
            u64 bp[8];
            F32X2_PACK(bp[0], b0.x, b0.x); F32X2_PACK(bp[1], b0.y, b0.y);
            F32X2_PACK(bp[2], b0.z, b0.z); F32X2_PACK(bp[3], b0.w, b0.w);
            F32X2_PACK(bp[4], b1.x, b1.x); F32X2_PACK(bp[5], b1.y, b1.y);
            F32X2_PACK(bp[6], b1.z, b1.z); F32X2_PACK(bp[7], b1.w, b1.w);
#pragma unroll
            for (int i = 0; i < 4; ++i)
#pragma unroll
                for (int j = 0; j < 8; ++j)
                    F32X2_FMA(acc[i][j], ap[i], bp[j], acc[i][j]);
        }
    }

    float bs[8];
#pragma unroll
    for (int j = 0; j < 8; ++j) {
        int n = n0 + tx*8 + j;
        bs[j] = (n < INPROJ) ? __ldg(&bias[n]) : 0.f;
    }
#pragma unroll
    for (int pr = 0; pr < 4; ++pr) {
        float vr[2][8];
#pragma unroll
        for (int j = 0; j < 8; ++j) {
            float v0, v1;
            F32X2_UNPACK(v0, v1, acc[pr][j]);
            vr[0][j] = v0 + bs[j];
            vr[1][j] = v1 + bs[j];
        }
#pragma unroll
        for (int rr = 0; rr < 2; ++rr) {
            int m = m0 + ty*8 + pr*2 + rr;
            int s = m >> 3, b = m & 7;
#pragma unroll
            for (int jp = 0; jp < 4; ++jp) {
                int n = n0 + tx*8 + 2*jp;
                if (n >= INPROJ) continue;
                float c0 = vr[rr][2*jp], c1 = vr[rr][2*jp+1];
                if (n < 512) {
                    int nn = n & 255;
                    int h = nn >> 5, d2 = (nn & 31) >> 1;
                    size_t off = (((size_t)(h*8+b))*SQ + s)*16 + d2;
                    u32 hi, lo;
                    split_pair(c0, c1, hi, lo);
                    if (n < 256) { g_qh[off] = hi; g_ql[off] = lo; }
                    else         { g_kh[off] = hi; g_kl[off] = lo; }
                } else {
                    int n3 = n - 512;
                    int h = n3 >> 2, d = n3 & 3;
                    size_t off = (((size_t)(h*8+b))*SQ + s)*PHD + d;
                    g_p[off]   = c0;
                    g_p[off+1] = c1;   // pairs within same PHD block (d even)
                }
            }
        }
    }
}

// ---------------------------------------------------------------------------
// Kernel 2: g_pe_h[h][n] = fp16x4 of sum_p pos_emb[n][p] * lw[h*4+d][p]
// ---------------------------------------------------------------------------
__global__ __launch_bounds__(256) void pe_kernel(
    const float* __restrict__ pos_emb, const float* __restrict__ lw)
{
    __shared__ float ws[4][193];
    const int tid = threadIdx.x;
    const int h = blockIdx.y;
    for (int i = tid; i < 4*PDIM; i += 256) {
        int o = i / PDIM, p = i % PDIM;
        ws[o][p] = lw[(h*4+o)*PDIM + p];
    }
    __syncthreads();
    int n = blockIdx.x * 256 + tid;
    if (n >= NPOS) return;
    float a0 = 0.f, a1 = 0.f, a2 = 0.f, a3 = 0.f;
    const float4* pr = (const float4*)&pos_emb[(size_t)n*PDIM];
#pragma unroll 4
    for (int p4 = 0; p4 < PDIM/4; ++p4) {
        float4 pv = __ldg(&pr[p4]);
        int p = p4*4;
        a0 = fmaf(pv.x, ws[0][p+0], a0); a1 = fmaf(pv.x, ws[1][p+0], a1);
        a2 = fmaf(pv.x, ws[2][p+0], a2); a3 = fmaf(pv.x, ws[3][p+0], a3);
        a0 = fmaf(pv.y, ws[0][p+1], a0); a1 = fmaf(pv.y, ws[1][p+1], a1);
        a2 = fmaf(pv.y, ws[2][p+1], a2); a3 = fmaf(pv.y, ws[3][p+1], a3);
        a0 = fmaf(pv.z, ws[0][p+2], a0); a1 = fmaf(pv.z, ws[1][p+2], a1);
        a2 = fmaf(pv.z, ws[2][p+2], a2); a3 = fmaf(pv.z, ws[3][p+2], a3);
        a0 = fmaf(pv.w, ws[0][p+3], a0); a1 = fmaf(pv.w, ws[1][p+3], a1);
        a2 = fmaf(pv.w, ws[2][p+3], a2); a3 = fmaf(pv.w, ws[3][p+3], a3);
    }
    __half2 h01 = __floats2half2_rn(a0, a1);
    __half2 h23 = __floats2half2_rn(a2, a3);
    g_pe_h[h*NPOS + n] = make_uint2(*(unsigned*)&h01, *(unsigned*)&h23);
}

// ---------------------------------------------------------------------------
// Kernel 3: tensor-core scores (split-bf16 mma.sync) + rel-shift + mask +
// softmax. 512 thr, 32 q-rows x 1024 j. Warp w: rows (w&1)*16..+16, cols
// (w>>1)*128..+128 (16 m16n8 tiles, 6 HMMA each for hh+hl+lh splits).
// ---------------------------------------------------------------------------
#define KB_P 1032
#define OFF_KB   0
#define OFF_PE   (2*16*KB_P*4)                  // 132096
#define OFF_QH   (OFF_PE + 1056*8)              // 140544
#define OFF_QL   (OFF_QH + 32*20*4)             // 143104
#define OFF_PH   (OFF_QL + 32*20*4)             // 145664
#define OFF_RED  (OFF_PH + 32*8)                // 145920
#define OFF_INV  (OFF_RED + 32*8*4)             // 146944
#define OFF_MASK (OFF_INV + 32*4)               // 147072
#define SMEM_ATTN (OFF_MASK + 1024)             // 148096

__global__ __launch_bounds__(512, 1) void attn_kernel(
    const unsigned char* __restrict__ kpm, float* __restrict__ out)
{
    extern __shared__ char smraw[];
    u32*   kb2h  = (u32*)(smraw + OFF_KB);        // [16 k2][1032 j] hi
    u32*   kb2l  = kb2h + 16*KB_P;                // lo
    uint2* pe_s  = (uint2*)(smraw + OFF_PE);      // [1056] fp16x4
    u32*   qh2   = (u32*)(smraw + OFF_QH);        // [32 r][20] bf16x2
    u32*   ql2   = (u32*)(smraw + OFF_QL);
    uint2* p_h2  = (uint2*)(smraw + OFF_PH);      // [32 r] fp16x4
    float* red_s = (float*)(smraw + OFF_RED);     // [32][8]
    float* inv_s = (float*)(smraw + OFF_INV);     // [32]
    unsigned char* mask_s = (unsigned char*)(smraw + OFF_MASK);

    const int tid = threadIdx.x;
    const int w = tid >> 5, lane = tid & 31;
    const int g = lane >> 2, tig = lane & 3;
    const int hb = blockIdx.y;
    const int h = hb >> 3, b = hb & 7;
    const int q0 = blockIdx.x * 32;

    // ---- fills ----
    {   // q hi/lo: [row][d2] -> qh2[row*20 + d2]
        int row = tid >> 4, d2 = tid & 15;
        size_t off = ((size_t)hb*SQ + q0 + row)*16 + d2;
        qh2[row*20 + d2] = __ldg(&g_qh[off]);
        ql2[row*20 + d2] = __ldg(&g_ql[off]);
    }
    if (tid < 256) ((uchar4*)mask_s)[tid] = ((const uchar4*)(kpm + (size_t)b*SQ))[tid];
    if (tid < 32) {
        float4 pv = *(const float4*)(g_p + ((size_t)hb*SQ + q0 + tid)*PHD);
        __half2 h01 = __floats2half2_rn(pv.x, pv.y);
        __half2 h23 = __floats2half2_rn(pv.z, pv.w);
        p_h2[tid] = make_uint2(*(unsigned*)&h01, *(unsigned*)&h23);
    }
    {
        const int nlo = 992 - q0;
        const uint2* pesrc = &g_pe_h[h*NPOS + nlo];
        for (int i = tid; i < 1055; i += 512) pe_s[i] = pesrc[i];
    }
    {   // K pairs: warp-uniform u -> conflict-free STS
        const u32 u = tid >> 7;        // 0..3
        const int jl = tid & 127;
        const uint4* kh4 = (const uint4*)(g_kh + (size_t)hb*SQ*16);
        const uint4* kl4 = (const uint4*)(g_kl + (size_t)hb*SQ*16);
#pragma unroll
        for (int i = 0; i < 8; ++i) {
            int j = jl + i*128;
            uint4 vh = __ldg(&kh4[(size_t)j*4 + u]);
            uint4 vl = __ldg(&kl4[(size_t)j*4 + u]);
            kb2h[(4*u+0)*KB_P + j] = vh.x;
            kb2h[(4*u+1)*KB_P + j] = vh.y;
            kb2h[(4*u+2)*KB_P + j] = vh.z;
            kb2h[(4*u+3)*KB_P + j] = vh.w;
            kb2l[(4*u+0)*KB_P + j] = vl.x;
            kb2l[(4*u+1)*KB_P + j] = vl.y;
            kb2l[(4*u+2)*KB_P + j] = vl.z;
            kb2l[(4*u+3)*KB_P + j] = vl.w;
        }
    }
    __syncthreads();

    const int rbase = (w & 1) * 16;
    const int jbase = (w >> 1) * 128;

    // ---- A fragments (preloaded, reused for all 16 n-tiles) ----
    u32 ah[8], al[8];
    {
        int ra = (rbase + g) * 20;
        int rb = (rbase + g + 8) * 20;
        ah[0] = qh2[ra + tig];      ah[1] = qh2[rb + tig];
        ah[2] = qh2[ra + 4 + tig];  ah[3] = qh2[rb + 4 + tig];
        ah[4] = qh2[ra + 8 + tig];  ah[5] = qh2[rb + 8 + tig];
        ah[6] = qh2[ra + 12 + tig]; ah[7] = qh2[rb + 12 + tig];
        al[0] = ql2[ra + tig];      al[1] = ql2[rb + tig];
        al[2] = ql2[ra + 4 + tig];  al[3] = ql2[rb + 4 + tig];
        al[4] = ql2[ra + 8 + tig];  al[5] = ql2[rb + 8 + tig];
        al[6] = ql2[ra + 12 + tig]; al[7] = ql2[rb + 12 + tig];
    }

    float acc[16][4];
#pragma unroll
    for (int t = 0; t < 16; ++t)
#pragma unroll
        for (int i = 0; i < 4; ++i) acc[t][i] = 0.f;

    // ---- mainloop: 16 n-tiles x (2 k-halves x 3 splits) HMMA ----
#pragma unroll
    for (int t = 0; t < 16; ++t) {
        const int jc = jbase + 8*t + g;
        u32 bh0 = kb2h[(0  + tig)*KB_P + jc];
        u32 bh1 = kb2h[(4  + tig)*KB_P + jc];
        u32 bh2 = kb2h[(8  + tig)*KB_P + jc];
        u32 bh3 = kb2h[(12 + tig)*KB_P + jc];
        u32 bl0 = kb2l[(0  + tig)*KB_P + jc];
        u32 bl1 = kb2l[(4  + tig)*KB_P + jc];
        u32 bl2 = kb2l[(8  + tig)*KB_P + jc];
        u32 bl3 = kb2l[(12 + tig)*KB_P + jc];
        MMA16816(acc[t], ah[0], ah[1], ah[2], ah[3], bh0, bh1);  // qh.kh k0-15
        MMA16816(acc[t], ah[4], ah[5], ah[6], ah[7], bh2, bh3);  // qh.kh k16-31
        MMA16816(acc[t], ah[0], ah[1], ah[2], ah[3], bl0, bl1);  // qh.kl
        MMA16816(acc[t], ah[4], ah[5], ah[6], ah[7], bl2, bl3);
        MMA16816(acc[t], al[0], al[1], al[2], al[3], bh0, bh1);  // ql.kh
        MMA16816(acc[t], al[4], al[5], al[6], al[7], bh2, bh3);
    }

    // ---- epilogue: pos scores (fp16) + mask + exp + row sums ----
    const int r1 = rbase + g, r2 = r1 + 8;
    uint2 p1u = p_h2[r1];
    uint2 p2u = p_h2[r2];
    __half2 p1a = *(__half2*)&p1u.x, p1b = *(__half2*)&p1u.y;
    __half2 p2a = *(__half2*)&p2u.x, p2b = *(__half2*)&p2u.y;
    float s1 = 0.f, s2 = 0.f;
#pragma unroll
    for (int t = 0; t < 16; ++t) {
        const int j0 = jbase + 8*t + 2*tig;
        const int j1 = j0 + 1;
        uint2 e11 = pe_s[j0 + 31 - r1];
        uint2 e12 = pe_s[j1 + 31 - r1];
        uint2 e21 = pe_s[j0 + 31 - r2];
        uint2 e22 = pe_s[j1 + 31 - r2];
        __half2 q11 = __hfma2(p1a, *(__half2*)&e11.x, __hmul2(p1b, *(__half2*)&e11.y));
        __half2 q12 = __hfma2(p1a, *(__half2*)&e12.x, __hmul2(p1b, *(__half2*)&e12.y));
        __half2 q21 = __hfma2(p2a, *(__half2*)&e21.x, __hmul2(p2b, *(__half2*)&e21.y));
        __half2 q22 = __hfma2(p2a, *(__half2*)&e22.x, __hmul2(p2b, *(__half2*)&e22.y));
        float pos11 = __low2float(q11) + __high2float(q11);
        float pos12 = __low2float(q12) + __high2float(q12);
        float pos21 = __low2float(q21) + __high2float(q21);
        float pos22 = __low2float(q22) + __high2float(q22);
        const bool m0 = mask_s[j0] != 0;
        const bool m1 = mask_s[j1] != 0;
        float e0 = m0 ? 0.f : __expf(acc[t][0] + pos11);
        float e1 = m1 ? 0.f : __expf(acc[t][1] + pos12);
        float e2 = m0 ? 0.f : __expf(acc[t][2] + pos21);
        float e3 = m1 ? 0.f : __expf(acc[t][3] + pos22);
        acc[t][0] = e0; acc[t][1] = e1; acc[t][2] = e2; acc[t][3] = e3;
        s1 += e0 + e1;
        s2 += e2 + e3;
    }
    // reduce over the 4 lanes sharing a row (tig group)
    s1 += __shfl_xor_sync(0xffffffffu, s1, 1);
    s1 += __shfl_xor_sync(0xffffffffu, s1, 2);
    s2 += __shfl_xor_sync(0xffffffffu, s2, 1);
    s2 += __shfl_xor_sync(0xffffffffu, s2, 2);
    if (tig == 0) {
        red_s[r1*8 + (w >> 1)] = s1;
        red_s[r2*8 + (w >> 1)] = s2;
    }
    __syncthreads();
    if (tid < 32) {
        float s = red_s[tid*8];
#pragma unroll
        for (int i = 1; i < 8; ++i) s += red_s[tid*8 + i];
        inv_s[tid] = 1.0f / s;
    }
    __syncthreads();

    // ---- normalize + streaming store ----
    const float i1 = inv_s[r1], i2 = inv_s[r2];
    float* o1 = out + ((size_t)hb*SQ + q0 + r1)*SQ;
    float* o2 = out + ((size_t)hb*SQ + q0 + r2)*SQ;
#pragma unroll
    for (int t = 0; t < 16; ++t) {
        const int j0 = jbase + 8*t + 2*tig;
        __stcs(&o1[j0],     acc[t][0] * i1);
        __stcs(&o1[j0 + 1], acc[t][1] * i1);
        __stcs(&o2[j0],     acc[t][2] * i2);
        __stcs(&o2[j0 + 1], acc[t][3] * i2);
    }
}

// ---------------------------------------------------------------------------
extern "C" void kernel_launch(void* const* d_in, const int* in_sizes, int n_in,
                              void* d_out, int out_size)
{
    const float* x            = (const float*)d_in[0];          // (S,B,E)
    const float* pos_emb      = (const float*)d_in[1];          // (1,2S-1,PDIM)
    const unsigned char* kpm  = (const unsigned char*)d_in[2];  // (B,S) bool
    const float* in_proj_w    = (const float*)d_in[3];          // (544,512)
    const float* in_proj_b    = (const float*)d_in[4];          // (544,)
    const float* linear_pos_w = (const float*)d_in[5];          // (32,192)
    float* out = (float*)d_out;                                 // (H,B,S,S)

    static bool attr_set = false;
    if (!attr_set) {
        cudaFuncSetAttribute(attn_kernel,
                             cudaFuncAttributeMaxDynamicSharedMemorySize, SMEM_ATTN);
        attr_set = true;
    }

    dim3 g1(9, 32);                          // 288 blocks = 1 wave @ occ 2
    proj_kernel<<<g1, 256>>>(x, in_proj_w, in_proj_b);

    dim3 g2((NPOS + 255)/256, NH);           // 8 x 8
    pe_kernel<<<g2, 256>>>(pos_emb, linear_pos_w);

    dim3 g3(SQ/32, NH*NB);                   // 32 x 64
    attn_kernel<<<g3, 512, SMEM_ATTN>>>(kpm, out);
}

// round 8
// speedup vs baseline: 1.7797x; 1.1230x over previous
#include <cuda_runtime.h>
#include <cuda_fp16.h>
#include <cuda_bf16.h>

#define SQ 1024
#define NB 8
#define NE 512
#define NH 8
#define QHD 32
#define PHD 4
#define PDIM 192
#define NPOS (2*SQ-1)   // 2047
#define INPROJ 544
#define MROWS (SQ*NB)   // 8192
#define K2E (NE/2)      // 256

typedef unsigned long long u64;
typedef unsigned int u32;

// bf16 mma m16n8k16, fp32 accumulate (in-place)
#define MMA16816(d, a0, a1, a2, a3, b0, b1) \
    asm("mma.sync.aligned.m16n8k16.row.col.f32.bf16.bf16.f32 " \
        "{%0,%1,%2,%3}, {%4,%5,%6,%7}, {%8,%9}, {%0,%1,%2,%3};" \
        : "+f"(d[0]), "+f"(d[1]), "+f"(d[2]), "+f"(d[3]) \
        : "r"(a0), "r"(a1), "r"(a2), "r"(a3), "r"(b0), "r"(b1))

// Scratch (device globals; no allocations allowed)
__device__ __align__(16) u32  g_xh[MROWS*K2E];     // x split hi [row][k2]
__device__ __align__(16) u32  g_xl[MROWS*K2E];
__device__ __align__(16) u32  g_whT[K2E*INPROJ];   // w split hi, transposed [k2][col]
__device__ __align__(16) u32  g_wlT[K2E*INPROJ];
__device__ __align__(16) u32  g_qh[NH*NB*SQ*16];   // [hb][s][d2] bf16x2 hi
__device__ __align__(16) u32  g_ql[NH*NB*SQ*16];   // bf16x2 lo (residual)
__device__ __align__(16) u32  g_kh[NH*NB*SQ*16];
__device__ __align__(16) u32  g_kl[NH*NB*SQ*16];
__device__ __align__(16) float g_p[NH*NB*SQ*PHD];  // [hb][s][d] fp32
__device__ __align__(16) uint2 g_pe_h[NH*NPOS];    // [h][n]: 4 x fp16

// v0,v1 -> hi (bf16x2: lo-half=v0), lo = residual pair
__device__ __forceinline__ void split_pair(float c0, float c1, u32& hi, u32& lo)
{
    u32 h;
    asm("cvt.rn.bf16x2.f32 %0, %1, %2;" : "=r"(h) : "f"(c1), "f"(c0));
    float f0 = __uint_as_float(h << 16);
    float f1 = __uint_as_float(h & 0xffff0000u);
    float r0 = c0 - f0, r1 = c1 - f1;
    asm("cvt.rn.bf16x2.f32 %0, %1, %2;" : "=r"(lo) : "f"(r1), "f"(r0));
    hi = h;
}

// ---------------------------------------------------------------------------
// Kernel 0: split x and w into bf16 hi/lo pair arrays (w also transposed).
// ---------------------------------------------------------------------------
#define XTOT (MROWS*K2E)
#define WTOT (INPROJ*K2E)

__global__ __launch_bounds__(256) void split_prep_kernel(
    const float* __restrict__ x, const float* __restrict__ w)
{
    int idx = blockIdx.x * 256 + threadIdx.x;
    if (idx < XTOT) {
        int row = idx >> 8, k2 = idx & 255;
        float2 v = *(const float2*)&x[(size_t)row*NE + 2*k2];
        u32 hi, lo; split_pair(v.x, v.y, hi, lo);
        g_xh[idx] = hi; g_xl[idx] = lo;
    } else {
        int i = idx - XTOT;
        if (i < WTOT) {
            int k2 = i / INPROJ, col = i % INPROJ;
            float2 v = *(const float2*)&w[(size_t)col*NE + 2*k2];
            u32 hi, lo; split_pair(v.x, v.y, hi, lo);
            g_whT[(size_t)k2*INPROJ + col] = hi;
            g_wlT[(size_t)k2*INPROJ + col] = lo;
        }
    }
}

// ---------------------------------------------------------------------------
// Kernel 1: proj = x @ W^T + b via split-bf16 mma.sync (hh+hl+lh).
// Block 128Mx64N, 256 thr = 8 warps (4m x 2n), warp tile 32x32.
// K chunks of 32 (16 k2), double-buffered smem with register prefetch.
// Epilogue: bias add + split q/k to bf16 hi/lo arrays (+ fp32 p).
// ---------------------------------------------------------------------------
#define PA 20      // A smem pitch (u32): banks 20g+tig all distinct
#define PB 72      // B smem pitch (u32): 72 % 32 == 8 -> banks 8*tig+g distinct
#define ST_A  2560                 // 128*PA
#define ST_B  1152                 // 16*PB
#define ST_SZ (2*ST_A + 2*ST_B)    // 7424 u32 per stage
#define SMEM_PROJ (2*ST_SZ*4)      // 59392 B

__global__ __launch_bounds__(256, 2) void proj_mma_kernel(
    const float* __restrict__ bias)
{
    extern __shared__ u32 sm[];
    const int tid = threadIdx.x;
    const int w = tid >> 5, lane = tid & 31;
    const int g = lane >> 2, tig = lane & 3;
    const int warp_m = w >> 1, warp_n = w & 1;
    const int m0 = blockIdx.y * 128;
    const int n0 = blockIdx.x * 64;

    // A fill mapping: row = tid>>1 (0..127), half = tid&1 -> k2 local half*8..+7
    const int a_row = tid >> 1, a_half = tid & 1;
    const uint4* xh4 = (const uint4*)g_xh;
    const uint4* xl4 = (const uint4*)g_xl;
    const size_t a_base = ((size_t)(m0 + a_row)*K2E) >> 2;  // uint4 index base

    // B fill mapping: k2l = tid>>4 (0..15), colq = tid&15 -> cols colq*4..+3
    const int b_k2l = tid >> 4, b_colq = tid & 15;
    const bool b_valid = (n0 + b_colq*4) < INPROJ;

    uint4 pa_h0, pa_h1, pa_l0, pa_l1, pb_h, pb_l;
    {   // prefetch chunk 0
        size_t ai = a_base + a_half*2;
        pa_h0 = __ldg(&xh4[ai]);   pa_h1 = __ldg(&xh4[ai+1]);
        pa_l0 = __ldg(&xl4[ai]);   pa_l1 = __ldg(&xl4[ai+1]);
        if (b_valid) {
            size_t bi = ((size_t)b_k2l*INPROJ + n0 + b_colq*4) >> 2;
            pb_h = __ldg(&((const uint4*)g_whT)[bi]);
            pb_l = __ldg(&((const uint4*)g_wlT)[bi]);
        } else {
            pb_h = make_uint4(0,0,0,0); pb_l = pb_h;
        }
    }

    float acc[2][4][4];
#pragma unroll
    for (int mt = 0; mt < 2; ++mt)
#pragma unroll
        for (int nt = 0; nt < 4; ++nt)
#pragma unroll
            for (int i = 0; i < 4; ++i) acc[mt][nt][i] = 0.f;

    for (int kc = 0; kc < 16; ++kc) {
        const int s = kc & 1;
        u32* Ah = sm + s*ST_SZ;
        u32* Al = Ah + ST_A;
        u32* Bh = Al + ST_A;
        u32* Bl = Bh + ST_B;
        // store prefetched regs
        *(uint4*)&Ah[a_row*PA + a_half*8]     = pa_h0;
        *(uint4*)&Ah[a_row*PA + a_half*8 + 4] = pa_h1;
        *(uint4*)&Al[a_row*PA + a_half*8]     = pa_l0;
        *(uint4*)&Al[a_row*PA + a_half*8 + 4] = pa_l1;
        *(uint4*)&Bh[b_k2l*PB + b_colq*4] = pb_h;
        *(uint4*)&Bl[b_k2l*PB + b_colq*4] = pb_l;
        __syncthreads();
        // prefetch next chunk
        if (kc < 15) {
            size_t ai = a_base + (kc+1)*4 + a_half*2;
            pa_h0 = __ldg(&xh4[ai]);   pa_h1 = __ldg(&xh4[ai+1]);
            pa_l0 = __ldg(&xl4[ai]);   pa_l1 = __ldg(&xl4[ai+1]);
            if (b_valid) {
                size_t bi = ((size_t)((kc+1)*16 + b_k2l)*INPROJ + n0 + b_colq*4) >> 2;
                pb_h = __ldg(&((const uint4*)g_whT)[bi]);
                pb_l = __ldg(&((const uint4*)g_wlT)[bi]);
            }
        }
        // compute: 2 ksteps of 16
#pragma unroll
        for (int ks = 0; ks < 2; ++ks) {
            const int kb = ks*8;
            u32 ah[2][4], al[2][4];
#pragma unroll
            for (int mt = 0; mt < 2; ++mt) {
                int r1 = (warp_m*32 + mt*16 + g) * PA;
                int r2 = r1 + 8*PA;
                ah[mt][0] = Ah[r1 + kb + tig];
                ah[mt][1] = Ah[r2 + kb + tig];
                ah[mt][2] = Ah[r1 + kb + 4 + tig];
                ah[mt][3] = Ah[r2 + kb + 4 + tig];
                al[mt][0] = Al[r1 + kb + tig];
                al[mt][1] = Al[r2 + kb + tig];
                al[mt][2] = Al[r1 + kb + 4 + tig];
                al[mt][3] = Al[r2 + kb + 4 + tig];
            }
#pragma unroll
            for (int nt = 0; nt < 4; ++nt) {
                int col = warp_n*32 + nt*8 + g;
                u32 bh0 = Bh[(kb + tig)*PB + col];
                u32 bh1 = Bh[(kb + 4 + tig)*PB + col];
                u32 bl0 = Bl[(kb + tig)*PB + col];
                u32 bl1 = Bl[(kb + 4 + tig)*PB + col];
#pragma unroll
                for (int mt = 0; mt < 2; ++mt) {
                    MMA16816(acc[mt][nt], ah[mt][0], ah[mt][1], ah[mt][2], ah[mt][3], bh0, bh1);
                    MMA16816(acc[mt][nt], ah[mt][0], ah[mt][1], ah[mt][2], ah[mt][3], bl0, bl1);
                    MMA16816(acc[mt][nt], al[mt][0], al[mt][1], al[mt][2], al[mt][3], bh0, bh1);
                }
            }
        }
        __syncthreads();
    }

    // ---- epilogue: bias + split to g_qh/g_ql/g_kh/g_kl/g_p ----
#pragma unroll
    for (int nt = 0; nt < 4; ++nt) {
        const int n = n0 + warp_n*32 + nt*8 + 2*tig;   // even col pair base
        if (n >= INPROJ) continue;
        const float b0 = __ldg(&bias[n]);
        const float b1 = __ldg(&bias[n+1]);
#pragma unroll
        for (int mt = 0; mt < 2; ++mt) {
#pragma unroll
            for (int rr = 0; rr < 2; ++rr) {
                const int m = m0 + warp_m*32 + mt*16 + g + rr*8;
                const int srow = m >> 3, bb = m & 7;
                const float c0 = acc[mt][nt][2*rr]     + b0;
                const float c1 = acc[mt][nt][2*rr + 1] + b1;
                if (n < 512) {
                    int nn = n & 255;
                    int h = nn >> 5, d2 = (nn & 31) >> 1;
                    size_t off = (((size_t)(h*8+bb))*SQ + srow)*16 + d2;
                    u32 hi, lo;
                    split_pair(c0, c1, hi, lo);
                    if (n < 256) { g_qh[off] = hi; g_ql[off] = lo; }
                    else         { g_kh[off] = hi; g_kl[off] = lo; }
                } else {
                    int n3 = n - 512;
                    int h = n3 >> 2, d = n3 & 3;
                    size_t off = (((size_t)(h*8+bb))*SQ + srow)*PHD + d;
                    g_p[off]   = c0;
                    g_p[off+1] = c1;
                }
            }
        }
    }
}

// ---------------------------------------------------------------------------
// Kernel 2: g_pe_h[h][n] = fp16x4 of sum_p pos_emb[n][p] * lw[h*4+d][p]
// ---------------------------------------------------------------------------
__global__ __launch_bounds__(256) void pe_kernel(
    const float* __restrict__ pos_emb, const float* __restrict__ lw)
{
    __shared__ float ws[4][193];
    const int tid = threadIdx.x;
    const int h = blockIdx.y;
    for (int i = tid; i < 4*PDIM; i += 256) {
        int o = i / PDIM, p = i % PDIM;
        ws[o][p] = lw[(h*4+o)*PDIM + p];
    }
    __syncthreads();
    int n = blockIdx.x * 256 + tid;
    if (n >= NPOS) return;
    float a0 = 0.f, a1 = 0.f, a2 = 0.f, a3 = 0.f;
    const float4* pr = (const float4*)&pos_emb[(size_t)n*PDIM];
#pragma unroll 4
    for (int p4 = 0; p4 < PDIM/4; ++p4) {
        float4 pv = __ldg(&pr[p4]);
        int p = p4*4;
        a0 = fmaf(pv.x, ws[0][p+0], a0); a1 = fmaf(pv.x, ws[1][p+0], a1);
        a2 = fmaf(pv.x, ws[2][p+0], a2); a3 = fmaf(pv.x, ws[3][p+0], a3);
        a0 = fmaf(pv.y, ws[0][p+1], a0); a1 = fmaf(pv.y, ws[1][p+1], a1);
        a2 = fmaf(pv.y, ws[2][p+1], a2); a3 = fmaf(pv.y, ws[3][p+1], a3);
        a0 = fmaf(pv.z, ws[0][p+2], a0); a1 = fmaf(pv.z, ws[1][p+2], a1);
        a2 = fmaf(pv.z, ws[2][p+2], a2); a3 = fmaf(pv.z, ws[3][p+2], a3);
        a0 = fmaf(pv.w, ws[0][p+3], a0); a1 = fmaf(pv.w, ws[1][p+3], a1);
        a2 = fmaf(pv.w, ws[2][p+3], a2); a3 = fmaf(pv.w, ws[3][p+3], a3);
    }
    __half2 h01 = __floats2half2_rn(a0, a1);
    __half2 h23 = __floats2half2_rn(a2, a3);
    g_pe_h[h*NPOS + n] = make_uint2(*(unsigned*)&h01, *(unsigned*)&h23);
}

// ---------------------------------------------------------------------------
// Kernel 3: tensor-core scores (split-bf16 mma.sync) + rel-shift + mask +
// softmax. 512 thr, 32 q-rows x 1024 j. (unchanged from R7)
// ---------------------------------------------------------------------------
#define KB_P 1032
#define OFF_KB   0
#define OFF_PE   (2*16*KB_P*4)                  // 132096
#define OFF_QH   (OFF_PE + 1056*8)              // 140544
#define OFF_QL   (OFF_QH + 32*20*4)             // 143104
#define OFF_PH   (OFF_QL + 32*20*4)             // 145664
#define OFF_RED  (OFF_PH + 32*8)                // 145920
#define OFF_INV  (OFF_RED + 32*8*4)             // 146944
#define OFF_MASK (OFF_INV + 32*4)               // 147072
#define SMEM_ATTN (OFF_MASK + 1024)             // 148096

__global__ __launch_bounds__(512, 1) void attn_kernel(
    const unsigned char* __restrict__ kpm, float* __restrict__ out)
{
    extern __shared__ char smraw[];
    u32*   kb2h  = (u32*)(smraw + OFF_KB);        // [16 k2][1032 j] hi
    u32*   kb2l  = kb2h + 16*KB_P;                // lo
    uint2* pe_s  = (uint2*)(smraw + OFF_PE);      // [1056] fp16x4
    u32*   qh2   = (u32*)(smraw + OFF_QH);        // [32 r][20] bf16x2
    u32*   ql2   = (u32*)(smraw + OFF_QL);
    uint2* p_h2  = (uint2*)(smraw + OFF_PH);      // [32 r] fp16x4
    float* red_s = (float*)(smraw + OFF_RED);     // [32][8]
    float* inv_s = (float*)(smraw + OFF_INV);     // [32]
    unsigned char* mask_s = (unsigned char*)(smraw + OFF_MASK);

    const int tid = threadIdx.x;
    const int w = tid >> 5, lane = tid & 31;
    const int g = lane >> 2, tig = lane & 3;
    const int hb = blockIdx.y;
    const int h = hb >> 3, b = hb & 7;
    const int q0 = blockIdx.x * 32;

    // ---- fills ----
    {   // q hi/lo: [row][d2] -> qh2[row*20 + d2]
        int row = tid >> 4, d2 = tid & 15;
        size_t off = ((size_t)hb*SQ + q0 + row)*16 + d2;
        qh2[row*20 + d2] = __ldg(&g_qh[off]);
        ql2[row*20 + d2] = __ldg(&g_ql[off]);
    }
    if (tid < 256) ((uchar4*)mask_s)[tid] = ((const uchar4*)(kpm + (size_t)b*SQ))[tid];
    if (tid < 32) {
        float4 pv = *(const float4*)(g_p + ((size_t)hb*SQ + q0 + tid)*PHD);
        __half2 h01 = __floats2half2_rn(pv.x, pv.y);
        __half2 h23 = __floats2half2_rn(pv.z, pv.w);
        p_h2[tid] = make_uint2(*(unsigned*)&h01, *(unsigned*)&h23);
    }
    {
        const int nlo = 992 - q0;
        const uint2* pesrc = &g_pe_h[h*NPOS + nlo];
        for (int i = tid; i < 1055; i += 512) pe_s[i] = pesrc[i];
    }
    {   // K pairs: warp-uniform u -> conflict-free STS
        const u32 u = tid >> 7;        // 0..3
        const int jl = tid & 127;
        const uint4* kh4 = (const uint4*)(g_kh + (size_t)hb*SQ*16);
        const uint4* kl4 = (const uint4*)(g_kl + (size_t)hb*SQ*16);
#pragma unroll
        for (int i = 0; i < 8; ++i) {
            int j = jl + i*128;
            uint4 vh = __ldg(&kh4[(size_t)j*4 + u]);
            uint4 vl = __ldg(&kl4[(size_t)j*4 + u]);
            kb2h[(4*u+0)*KB_P + j] = vh.x;
            kb2h[(4*u+1)*KB_P + j] = vh.y;
            kb2h[(4*u+2)*KB_P + j] = vh.z;
            kb2h[(4*u+3)*KB_P + j] = vh.w;
            kb2l[(4*u+0)*KB_P + j] = vl.x;
            kb2l[(4*u+1)*KB_P + j] = vl.y;
            kb2l[(4*u+2)*KB_P + j] = vl.z;
            kb2l[(4*u+3)*KB_P + j] = vl.w;
        }
    }
    __syncthreads();

    const int rbase = (w & 1) * 16;
    const int jbase = (w >> 1) * 128;

    // ---- A fragments (preloaded, reused for all 16 n-tiles) ----
    u32 ah[8], al[8];
    {
        int ra = (rbase + g) * 20;
        int rb = (rbase + g + 8) * 20;
        ah[0] = qh2[ra + tig];      ah[1] = qh2[rb + tig];
        ah[2] = qh2[ra + 4 + tig];  ah[3] = qh2[rb + 4 + tig];
        ah[4] = qh2[ra + 8 + tig];  ah[5] = qh2[rb + 8 + tig];
        ah[6] = qh2[ra + 12 + tig]; ah[7] = qh2[rb + 12 + tig];
        al[0] = ql2[ra + tig];      al[1] = ql2[rb + tig];
        al[2] = ql2[ra + 4 + tig];  al[3] = ql2[rb + 4 + tig];
        al[4] = ql2[ra + 8 + tig];  al[5] = ql2[rb + 8 + tig];
        al[6] = ql2[ra + 12 + tig]; al[7] = ql2[rb + 12 + tig];
    }

    float acc[16][4];
#pragma unroll
    for (int t = 0; t < 16; ++t)
#pragma unroll
        for (int i = 0; i < 4; ++i) acc[t][i] = 0.f;

    // ---- mainloop: 16 n-tiles x (2 k-halves x 3 splits) HMMA ----
#pragma unroll
    for (int t = 0; t < 16; ++t) {
        const int jc = jbase + 8*t + g;
        u32 bh0 = kb2h[(0  + tig)*KB_P + jc];
        u32 bh1 = kb2h[(4  + tig)*KB_P + jc];
        u32 bh2 = kb2h[(8  + tig)*KB_P + jc];
        u32 bh3 = kb2h[(12 + tig)*KB_P + jc];
        u32 bl0 = kb2l[(0  + tig)*KB_P + jc];
        u32 bl1 = kb2l[(4  + tig)*KB_P + jc];
        u32 bl2 = kb2l[(8  + tig)*KB_P + jc];
        u32 bl3 = kb2l[(12 + tig)*KB_P + jc];
        MMA16816(acc[t], ah[0], ah[1], ah[2], ah[3], bh0, bh1);  // qh.kh k0-15
        MMA16816(acc[t], ah[4], ah[5], ah[6], ah[7], bh2, bh3);  // qh.kh k16-31
        MMA16816(acc[t], ah[0], ah[1], ah[2], ah[3], bl0, bl1);  // qh.kl
        MMA16816(acc[t], ah[4], ah[5], ah[6], ah[7], bl2, bl3);
        MMA16816(acc[t], al[0], al[1], al[2], al[3], bh0, bh1);  // ql.kh
        MMA16816(acc[t], al[4], al[5], al[6], al[7], bh2, bh3);
    }

    // ---- epilogue: pos scores (fp16) + mask + exp + row sums ----
    const int r1 = rbase + g, r2 = r1 + 8;
    uint2 p1u = p_h2[r1];
    uint2 p2u = p_h2[r2];
    __half2 p1a = *(__half2*)&p1u.x, p1b = *(__half2*)&p1u.y;
    __half2 p2a = *(__half2*)&p2u.x, p2b = *(__half2*)&p2u.y;
    float s1 = 0.f, s2 = 0.f;
#pragma unroll
    for (int t = 0; t < 16; ++t) {
        const int j0 = jbase + 8*t + 2*tig;
        const int j1 = j0 + 1;
        uint2 e11 = pe_s[j0 + 31 - r1];
        uint2 e12 = pe_s[j1 + 31 - r1];
        uint2 e21 = pe_s[j0 + 31 - r2];
        uint2 e22 = pe_s[j1 + 31 - r2];
        __half2 q11 = __hfma2(p1a, *(__half2*)&e11.x, __hmul2(p1b, *(__half2*)&e11.y));
        __half2 q12 = __hfma2(p1a, *(__half2*)&e12.x, __hmul2(p1b, *(__half2*)&e12.y));
        __half2 q21 = __hfma2(p2a, *(__half2*)&e21.x, __hmul2(p2b, *(__half2*)&e21.y));
        __half2 q22 = __hfma2(p2a, *(__half2*)&e22.x, __hmul2(p2b, *(__half2*)&e22.y));
        float pos11 = __low2float(q11) + __high2float(q11);
        float pos12 = __low2float(q12) + __high2float(q12);
        float pos21 = __low2float(q21) + __high2float(q21);
        float pos22 = __low2float(q22) + __high2float(q22);
        const bool m0 = mask_s[j0] != 0;
        const bool m1 = mask_s[j1] != 0;
        float e0 = m0 ? 0.f : __expf(acc[t][0] + pos11);
        float e1 = m1 ? 0.f : __expf(acc[t][1] + pos12);
        float e2 = m0 ? 0.f : __expf(acc[t][2] + pos21);
        float e3 = m1 ? 0.f : __expf(acc[t][3] + pos22);
        acc[t][0] = e0; acc[t][1] = e1; acc[t][2] = e2; acc[t][3] = e3;
        s1 += e0 + e1;
        s2 += e2 + e3;
    }
    // reduce over the 4 lanes sharing a row (tig group)
    s1 += __shfl_xor_sync(0xffffffffu, s1, 1);
    s1 += __shfl_xor_sync(0xffffffffu, s1, 2);
    s2 += __shfl_xor_sync(0xffffffffu, s2, 1);
    s2 += __shfl_xor_sync(0xffffffffu, s2, 2);
    if (tig == 0) {
        red_s[r1*8 + (w >> 1)] = s1;
        red_s[r2*8 + (w >> 1)] = s2;
    }
    __syncthreads();
    if (tid < 32) {
        float s = red_s[tid*8];
#pragma unroll
        for (int i = 1; i < 8; ++i) s += red_s[tid*8 + i];
        inv_s[tid] = 1.0f / s;
    }
    __syncthreads();

    // ---- normalize + streaming store ----
    const float i1 = inv_s[r1], i2 = inv_s[r2];
    float* o1 = out + ((size_t)hb*SQ + q0 + r1)*SQ;
    float* o2 = out + ((size_t)hb*SQ + q0 + r2)*SQ;
#pragma unroll
    for (int t = 0; t < 16; ++t) {
        const int j0 = jbase + 8*t + 2*tig;
        __stcs(&o1[j0],     acc[t][0] * i1);
        __stcs(&o1[j0 + 1], acc[t][1] * i1);
        __stcs(&o2[j0],     acc[t][2] * i2);
        __stcs(&o2[j0 + 1], acc[t][3] * i2);
    }
}

// ---------------------------------------------------------------------------
extern "C" void kernel_launch(void* const* d_in, const int* in_sizes, int n_in,
                              void* d_out, int out_size)
{
    const float* x            = (const float*)d_in[0];          // (S,B,E)
    const float* pos_emb      = (const float*)d_in[1];          // (1,2S-1,PDIM)
    const unsigned char* kpm  = (const unsigned char*)d_in[2];  // (B,S) bool
    const float* in_proj_w    = (const float*)d_in[3];          // (544,512)
    const float* in_proj_b    = (const float*)d_in[4];          // (544,)
    const float* linear_pos_w = (const float*)d_in[5];          // (32,192)
    float* out = (float*)d_out;                                 // (H,B,S,S)

    static bool attr_set = false;
    if (!attr_set) {
        cudaFuncSetAttribute(attn_kernel,
                             cudaFuncAttributeMaxDynamicSharedMemorySize, SMEM_ATTN);
        cudaFuncSetAttribute(proj_mma_kernel,
                             cudaFuncAttributeMaxDynamicSharedMemorySize, SMEM_PROJ);
        attr_set = true;
    }

    split_prep_kernel<<<(XTOT + WTOT + 255)/256, 256>>>(x, in_proj_w);

    dim3 g1(9, 64);                          // 64-col N tiles x 128-row M tiles
    proj_mma_kernel<<<g1, 256, SMEM_PROJ>>>(in_proj_b);

    dim3 g2((NPOS + 255)/256, NH);           // 8 x 8
    pe_kernel<<<g2, 256>>>(pos_emb, linear_pos_w);

    dim3 g3(SQ/32, NH*NB);                   // 32 x 64
    attn_kernel<<<g3, 512, SMEM_ATTN>>>(kpm, out);
}

// round 9
// speedup vs baseline: 1.8803x; 1.0565x over previous
#include <cuda_runtime.h>
#include <cuda_fp16.h>
#include <cuda_bf16.h>

#define SQ 1024
#define NB 8
#define NE 512
#define NH 8
#define QHD 32
#define PHD 4
#define PDIM 192
#define NPOS (2*SQ-1)   // 2047
#define INPROJ 544
#define MROWS (SQ*NB)   // 8192
#define K2E (NE/2)      // 256

typedef unsigned long long u64;
typedef unsigned int u32;

// bf16 mma m16n8k16, fp32 accumulate (in-place)
#define MMA16816(d, a0, a1, a2, a3, b0, b1) \
    asm("mma.sync.aligned.m16n8k16.row.col.f32.bf16.bf16.f32 " \
        "{%0,%1,%2,%3}, {%4,%5,%6,%7}, {%8,%9}, {%0,%1,%2,%3};" \
        : "+f"(d[0]), "+f"(d[1]), "+f"(d[2]), "+f"(d[3]) \
        : "r"(a0), "r"(a1), "r"(a2), "r"(a3), "r"(b0), "r"(b1))

#define CPA16(d, s) asm volatile("cp.async.cg.shared.global [%0], [%1], 16;" :: "r"(d), "l"(s))
#define CPA8(d, s)  asm volatile("cp.async.ca.shared.global [%0], [%1], 8;"  :: "r"(d), "l"(s))
#define CPA4(d, s)  asm volatile("cp.async.ca.shared.global [%0], [%1], 4;"  :: "r"(d), "l"(s))
#define CPA_COMMIT() asm volatile("cp.async.commit_group;")
#define CPA_WAIT0()  asm volatile("cp.async.wait_group 0;" ::: "memory")

// Scratch (device globals; no allocations allowed)
__device__ __align__(16) u32  g_xh[MROWS*K2E];     // x split hi [row][k2]
__device__ __align__(16) u32  g_xl[MROWS*K2E];
__device__ __align__(16) u32  g_whT[K2E*INPROJ];   // w split hi, transposed [k2][col]
__device__ __align__(16) u32  g_wlT[K2E*INPROJ];
__device__ __align__(16) u32  g_qh[NH*NB*SQ*16];   // [hb][s][d2] bf16x2 hi
__device__ __align__(16) u32  g_ql[NH*NB*SQ*16];   // bf16x2 lo (residual)
__device__ __align__(16) u32  g_kh[NH*NB*SQ*16];
__device__ __align__(16) u32  g_kl[NH*NB*SQ*16];
__device__ __align__(16) float g_p[NH*NB*SQ*PHD];  // [hb][s][d] fp32
__device__ __align__(16) uint2 g_pe_h[NH*NPOS + 8];// [h][n]: 4 x fp16 (+pad)

// v0,v1 -> hi (bf16x2: lo-half=v0), lo = residual pair
__device__ __forceinline__ void split_pair(float c0, float c1, u32& hi, u32& lo)
{
    u32 h;
    asm("cvt.rn.bf16x2.f32 %0, %1, %2;" : "=r"(h) : "f"(c1), "f"(c0));
    float f0 = __uint_as_float(h << 16);
    float f1 = __uint_as_float(h & 0xffff0000u);
    float r0 = c0 - f0, r1 = c1 - f1;
    asm("cvt.rn.bf16x2.f32 %0, %1, %2;" : "=r"(lo) : "f"(r1), "f"(r0));
    hi = h;
}

// ---------------------------------------------------------------------------
// Kernel 0: split x and w into bf16 hi/lo pair arrays (w also transposed).
// ---------------------------------------------------------------------------
#define XTOT (MROWS*K2E)
#define WTOT (INPROJ*K2E)

__global__ __launch_bounds__(256) void split_prep_kernel(
    const float* __restrict__ x, const float* __restrict__ w)
{
    int idx = blockIdx.x * 256 + threadIdx.x;
    if (idx < XTOT) {
        int row = idx >> 8, k2 = idx & 255;
        float2 v = *(const float2*)&x[(size_t)row*NE + 2*k2];
        u32 hi, lo; split_pair(v.x, v.y, hi, lo);
        g_xh[idx] = hi; g_xl[idx] = lo;
    } else {
        int i = idx - XTOT;
        if (i < WTOT) {
            int k2 = i / INPROJ, col = i % INPROJ;
            float2 v = *(const float2*)&w[(size_t)col*NE + 2*k2];
            u32 hi, lo; split_pair(v.x, v.y, hi, lo);
            g_whT[(size_t)k2*INPROJ + col] = hi;
            g_wlT[(size_t)k2*INPROJ + col] = lo;
        }
    }
}

// ---------------------------------------------------------------------------
// Kernel 1: proj = x @ W^T + b via split-bf16 mma.sync (hh+hl+lh).
// (unchanged from R8)
// ---------------------------------------------------------------------------
#define PA 20
#define PB 72
#define ST_A  2560
#define ST_B  1152
#define ST_SZ (2*ST_A + 2*ST_B)
#define SMEM_PROJ (2*ST_SZ*4)

__global__ __launch_bounds__(256, 2) void proj_mma_kernel(
    const float* __restrict__ bias)
{
    extern __shared__ u32 sm[];
    const int tid = threadIdx.x;
    const int w = tid >> 5, lane = tid & 31;
    const int g = lane >> 2, tig = lane & 3;
    const int warp_m = w >> 1, warp_n = w & 1;
    const int m0 = blockIdx.y * 128;
    const int n0 = blockIdx.x * 64;

    const int a_row = tid >> 1, a_half = tid & 1;
    const uint4* xh4 = (const uint4*)g_xh;
    const uint4* xl4 = (const uint4*)g_xl;
    const size_t a_base = ((size_t)(m0 + a_row)*K2E) >> 2;

    const int b_k2l = tid >> 4, b_colq = tid & 15;
    const bool b_valid = (n0 + b_colq*4) < INPROJ;

    uint4 pa_h0, pa_h1, pa_l0, pa_l1, pb_h, pb_l;
    {
        size_t ai = a_base + a_half*2;
        pa_h0 = __ldg(&xh4[ai]);   pa_h1 = __ldg(&xh4[ai+1]);
        pa_l0 = __ldg(&xl4[ai]);   pa_l1 = __ldg(&xl4[ai+1]);
        if (b_valid) {
            size_t bi = ((size_t)b_k2l*INPROJ + n0 + b_colq*4) >> 2;
            pb_h = __ldg(&((const uint4*)g_whT)[bi]);
            pb_l = __ldg(&((const uint4*)g_wlT)[bi]);
        } else {
            pb_h = make_uint4(0,0,0,0); pb_l = pb_h;
        }
    }

    float acc[2][4][4];
#pragma unroll
    for (int mt = 0; mt < 2; ++mt)
#pragma unroll
        for (int nt = 0; nt < 4; ++nt)
#pragma unroll
            for (int i = 0; i < 4; ++i) acc[mt][nt][i] = 0.f;

    for (int kc = 0; kc < 16; ++kc) {
        const int s = kc & 1;
        u32* Ah = sm + s*ST_SZ;
        u32* Al = Ah + ST_A;
        u32* Bh = Al + ST_A;
        u32* Bl = Bh + ST_B;
        *(uint4*)&Ah[a_row*PA + a_half*8]     = pa_h0;
        *(uint4*)&Ah[a_row*PA + a_half*8 + 4] = pa_h1;
        *(uint4*)&Al[a_row*PA + a_half*8]     = pa_l0;
        *(uint4*)&Al[a_row*PA + a_half*8 + 4] = pa_l1;
        *(uint4*)&Bh[b_k2l*PB + b_colq*4] = pb_h;
        *(uint4*)&Bl[b_k2l*PB + b_colq*4] = pb_l;
        __syncthreads();
        if (kc < 15) {
            size_t ai = a_base + (kc+1)*4 + a_half*2;
            pa_h0 = __ldg(&xh4[ai]);   pa_h1 = __ldg(&xh4[ai+1]);
            pa_l0 = __ldg(&xl4[ai]);   pa_l1 = __ldg(&xl4[ai+1]);
            if (b_valid) {
                size_t bi = ((size_t)((kc+1)*16 + b_k2l)*INPROJ + n0 + b_colq*4) >> 2;
                pb_h = __ldg(&((const uint4*)g_whT)[bi]);
                pb_l = __ldg(&((const uint4*)g_wlT)[bi]);
            }
        }
#pragma unroll
        for (int ks = 0; ks < 2; ++ks) {
            const int kb = ks*8;
            u32 ah[2][4], al[2][4];
#pragma unroll
            for (int mt = 0; mt < 2; ++mt) {
                int r1 = (warp_m*32 + mt*16 + g) * PA;
                int r2 = r1 + 8*PA;
                ah[mt][0] = Ah[r1 + kb + tig];
                ah[mt][1] = Ah[r2 + kb + tig];
                ah[mt][2] = Ah[r1 + kb + 4 + tig];
                ah[mt][3] = Ah[r2 + kb + 4 + tig];
                al[mt][0] = Al[r1 + kb + tig];
                al[mt][1] = Al[r2 + kb + tig];
                al[mt][2] = Al[r1 + kb + 4 + tig];
                al[mt][3] = Al[r2 + kb + 4 + tig];
            }
#pragma unroll
            for (int nt = 0; nt < 4; ++nt) {
                int col = warp_n*32 + nt*8 + g;
                u32 bh0 = Bh[(kb + tig)*PB + col];
                u32 bh1 = Bh[(kb + 4 + tig)*PB + col];
                u32 bl0 = Bl[(kb + tig)*PB + col];
                u32 bl1 = Bl[(kb + 4 + tig)*PB + col];
#pragma unroll
                for (int mt = 0; mt < 2; ++mt) {
                    MMA16816(acc[mt][nt], ah[mt][0], ah[mt][1], ah[mt][2], ah[mt][3], bh0, bh1);
                    MMA16816(acc[mt][nt], ah[mt][0], ah[mt][1], ah[mt][2], ah[mt][3], bl0, bl1);
                    MMA16816(acc[mt][nt], al[mt][0], al[mt][1], al[mt][2], al[mt][3], bh0, bh1);
                }
            }
        }
        __syncthreads();
    }

#pragma unroll
    for (int nt = 0; nt < 4; ++nt) {
        const int n = n0 + warp_n*32 + nt*8 + 2*tig;
        if (n >= INPROJ) continue;
        const float b0 = __ldg(&bias[n]);
        const float b1 = __ldg(&bias[n+1]);
#pragma unroll
        for (int mt = 0; mt < 2; ++mt) {
#pragma unroll
            for (int rr = 0; rr < 2; ++rr) {
                const int m = m0 + warp_m*32 + mt*16 + g + rr*8;
                const int srow = m >> 3, bb = m & 7;
                const float c0 = acc[mt][nt][2*rr]     + b0;
                const float c1 = acc[mt][nt][2*rr + 1] + b1;
                if (n < 512) {
                    int nn = n & 255;
                    int h = nn >> 5, d2 = (nn & 31) >> 1;
                    size_t off = (((size_t)(h*8+bb))*SQ + srow)*16 + d2;
                    u32 hi, lo;
                    split_pair(c0, c1, hi, lo);
                    if (n < 256) { g_qh[off] = hi; g_ql[off] = lo; }
                    else         { g_kh[off] = hi; g_kl[off] = lo; }
                } else {
                    int n3 = n - 512;
                    int h = n3 >> 2, d = n3 & 3;
                    size_t off = (((size_t)(h*8+bb))*SQ + srow)*PHD + d;
                    g_p[off]   = c0;
                    g_p[off+1] = c1;
                }
            }
        }
    }
}

// ---------------------------------------------------------------------------
// Kernel 2: g_pe_h[h][n] = fp16x4 of sum_p pos_emb[n][p] * lw[h*4+d][p]
// ---------------------------------------------------------------------------
__global__ __launch_bounds__(256) void pe_kernel(
    const float* __restrict__ pos_emb, const float* __restrict__ lw)
{
    __shared__ float ws[4][193];
    const int tid = threadIdx.x;
    const int h = blockIdx.y;
    for (int i = tid; i < 4*PDIM; i += 256) {
        int o = i / PDIM, p = i % PDIM;
        ws[o][p] = lw[(h*4+o)*PDIM + p];
    }
    __syncthreads();
    int n = blockIdx.x * 256 + tid;
    if (n >= NPOS) return;
    float a0 = 0.f, a1 = 0.f, a2 = 0.f, a3 = 0.f;
    const float4* pr = (const float4*)&pos_emb[(size_t)n*PDIM];
#pragma unroll 4
    for (int p4 = 0; p4 < PDIM/4; ++p4) {
        float4 pv = __ldg(&pr[p4]);
        int p = p4*4;
        a0 = fmaf(pv.x, ws[0][p+0], a0); a1 = fmaf(pv.x, ws[1][p+0], a1);
        a2 = fmaf(pv.x, ws[2][p+0], a2); a3 = fmaf(pv.x, ws[3][p+0], a3);
        a0 = fmaf(pv.y, ws[0][p+1], a0); a1 = fmaf(pv.y, ws[1][p+1], a1);
        a2 = fmaf(pv.y, ws[2][p+1], a2); a3 = fmaf(pv.y, ws[3][p+1], a3);
        a0 = fmaf(pv.z, ws[0][p+2], a0); a1 = fmaf(pv.z, ws[1][p+2], a1);
        a2 = fmaf(pv.z, ws[2][p+2], a2); a3 = fmaf(pv.z, ws[3][p+2], a3);
        a0 = fmaf(pv.w, ws[0][p+3], a0); a1 = fmaf(pv.w, ws[1][p+3], a1);
        a2 = fmaf(pv.w, ws[2][p+3], a2); a3 = fmaf(pv.w, ws[3][p+3], a3);
    }
    __half2 h01 = __floats2half2_rn(a0, a1);
    __half2 h23 = __floats2half2_rn(a2, a3);
    g_pe_h[h*NPOS + n] = make_uint2(*(unsigned*)&h01, *(unsigned*)&h23);
}

// ---------------------------------------------------------------------------
// Kernel 3: tensor-core scores + rel-shift + mask + softmax.
// Per-pair cp.async fills (K [j][k2] pitch-20, pe window, mask) + named-
// barrier sync only — no block barriers until the row-sum reduction.
// q A-frags and p are read directly via LDG (broadcast, L1-hot).
// ---------------------------------------------------------------------------
#define KJ_P 20
#define OFF_KB   0                         // 2 * 1024*20*4 = 163840
#define KB_LO    (1024*KJ_P)               // u32 offset of lo array
#define OFF_PEL  163840                    // 8 pairs * 160 uint2 = 10240
#define OFF_RED  174080                    // 32*8*4 = 1024
#define OFF_INV  175104                    // 128
#define OFF_MASK 175232                    // 8 pairs * 128 = 1024
#define SMEM_ATTN 176256

__global__ __launch_bounds__(512, 1) void attn_kernel(
    const unsigned char* __restrict__ kpm, float* __restrict__ out)
{
    extern __shared__ char smraw[];
    u32*   kb2h  = (u32*)(smraw + OFF_KB);       // [1024 j][20] (16 k2 used)
    u32*   kb2l  = kb2h + KB_LO;
    uint2* pe_l  = (uint2*)(smraw + OFF_PEL);    // [8 pairs][160]
    float* red_s = (float*)(smraw + OFF_RED);    // [32][8]
    float* inv_s = (float*)(smraw + OFF_INV);    // [32]
    unsigned char* mask_l = (unsigned char*)(smraw + OFF_MASK); // [8][128]
    const u32 smb = (u32)__cvta_generic_to_shared(smraw);

    const int tid = threadIdx.x;
    const int w = tid >> 5, lane = tid & 31;
    const int g = lane >> 2, tig = lane & 3;
    const int pairid = w >> 1;
    const int jstart = pairid * 128;
    const int hb = blockIdx.y;
    const int h = hb >> 3, b = hb & 7;
    const int q0 = blockIdx.x * 32;
    const size_t hbSQ = (size_t)hb * SQ;

    // ---- per-pair async fills ----
    {   // K span: even warp copies hi, odd copies lo (128 j rows x 64B)
        const u32* ksrc = ((w & 1) ? g_kl : g_kh) + (hbSQ + jstart)*16;
        const u32 kdst = smb + OFF_KB + (w & 1)*(KB_LO*4) + jstart*KJ_P*4;
#pragma unroll
        for (int i = 0; i < 16; ++i) {
            int lin = i*32 + lane;
            int jl = lin >> 2, seg = lin & 3;
            CPA16(kdst + (jl*KJ_P + seg*4)*4, ksrc + jl*16 + seg*4);
        }
        // pe window for this pair: 160 uint2 from n = nlo + jstart
        const uint2* pesrc = g_pe_h + h*NPOS + (992 - q0) + jstart;
        const u32 pedst = smb + OFF_PEL + pairid*160*8;
        const int tpair = (w & 1)*32 + lane;
#pragma unroll
        for (int it = 0; it < 3; ++it) {
            int i = tpair + it*64;
            if (i < 160) CPA8(pedst + i*8, pesrc + i);
        }
        // mask span: 128 bytes (even warp only)
        if (tpair < 32)
            CPA4(smb + OFF_MASK + pairid*128 + tpair*4,
                 kpm + (size_t)b*SQ + jstart + tpair*4);
        CPA_COMMIT();
    }
    CPA_WAIT0();
    asm volatile("bar.sync %0, 64;" :: "r"(1 + pairid) : "memory");

    const int rbase = (w & 1) * 16;
    const int r1 = rbase + g, r2 = r1 + 8;

    // ---- A fragments: direct LDG (broadcast within tig groups) ----
    u32 ah[8], al[8];
    {
        const u32* qa = g_qh + (hbSQ + q0 + r1)*16;
        const u32* qb = qa + 8*16;
        ah[0] = __ldg(&qa[tig]);      ah[1] = __ldg(&qb[tig]);
        ah[2] = __ldg(&qa[4 + tig]);  ah[3] = __ldg(&qb[4 + tig]);
        ah[4] = __ldg(&qa[8 + tig]);  ah[5] = __ldg(&qb[8 + tig]);
        ah[6] = __ldg(&qa[12 + tig]); ah[7] = __ldg(&qb[12 + tig]);
        const u32* la = g_ql + (hbSQ + q0 + r1)*16;
        const u32* lb = la + 8*16;
        al[0] = __ldg(&la[tig]);      al[1] = __ldg(&lb[tig]);
        al[2] = __ldg(&la[4 + tig]);  al[3] = __ldg(&lb[4 + tig]);
        al[4] = __ldg(&la[8 + tig]);  al[5] = __ldg(&lb[8 + tig]);
        al[6] = __ldg(&la[12 + tig]); al[7] = __ldg(&lb[12 + tig]);
    }
    // ---- p rows (fp32 -> fp16x2 pairs) ----
    __half2 p1a, p1b, p2a, p2b;
    {
        float4 pv1 = *(const float4*)(g_p + (hbSQ + q0 + r1)*PHD);
        float4 pv2 = *(const float4*)(g_p + (hbSQ + q0 + r2)*PHD);
        p1a = __floats2half2_rn(pv1.x, pv1.y);
        p1b = __floats2half2_rn(pv1.z, pv1.w);
        p2a = __floats2half2_rn(pv2.x, pv2.y);
        p2b = __floats2half2_rn(pv2.z, pv2.w);
    }

    float acc[16][4];
#pragma unroll
    for (int t = 0; t < 16; ++t)
#pragma unroll
        for (int i = 0; i < 4; ++i) acc[t][i] = 0.f;

    // ---- mainloop: 16 n-tiles x 6 HMMA (hh x2, hl x2, lh x2) ----
#pragma unroll
    for (int t = 0; t < 16; ++t) {
        const int jc = jstart + 8*t + g;
        const u32* kr = kb2h + jc*KJ_P;
        const u32* lr = kb2l + jc*KJ_P;
        u32 bh0 = kr[tig],     bh1 = kr[4 + tig];
        u32 bh2 = kr[8 + tig], bh3 = kr[12 + tig];
        u32 bl0 = lr[tig],     bl1 = lr[4 + tig];
        u32 bl2 = lr[8 + tig], bl3 = lr[12 + tig];
        MMA16816(acc[t], ah[0], ah[1], ah[2], ah[3], bh0, bh1);
        MMA16816(acc[t], ah[4], ah[5], ah[6], ah[7], bh2, bh3);
        MMA16816(acc[t], ah[0], ah[1], ah[2], ah[3], bl0, bl1);
        MMA16816(acc[t], ah[4], ah[5], ah[6], ah[7], bl2, bl3);
        MMA16816(acc[t], al[0], al[1], al[2], al[3], bh0, bh1);
        MMA16816(acc[t], al[4], al[5], al[6], al[7], bh2, bh3);
    }

    // ---- epilogue: pos scores (fp16) + mask + exp + row sums ----
    const uint2* peb = pe_l + pairid*160;
    const unsigned char* mkb = mask_l + pairid*128;
    float s1 = 0.f, s2 = 0.f;
#pragma unroll
    for (int t = 0; t < 16; ++t) {
        const int jl0 = 8*t + 2*tig;
        const int idx1 = jl0 + 31 - r1;       // r1 is global-in-block row
        const int idx2 = idx1 - 8;            // row r2 = r1 + 8
        uint2 e11 = peb[idx1];
        uint2 e12 = peb[idx1 + 1];
        uint2 e21 = peb[idx2];
        uint2 e22 = peb[idx2 + 1];
        __half2 q11 = __hfma2(p1a, *(__half2*)&e11.x, __hmul2(p1b, *(__half2*)&e11.y));
        __half2 q12 = __hfma2(p1a, *(__half2*)&e12.x, __hmul2(p1b, *(__half2*)&e12.y));
        __half2 q21 = __hfma2(p2a, *(__half2*)&e21.x, __hmul2(p2b, *(__half2*)&e21.y));
        __half2 q22 = __hfma2(p2a, *(__half2*)&e22.x, __hmul2(p2b, *(__half2*)&e22.y));
        float pos11 = __low2float(q11) + __high2float(q11);
        float pos12 = __low2float(q12) + __high2float(q12);
        float pos21 = __low2float(q21) + __high2float(q21);
        float pos22 = __low2float(q22) + __high2float(q22);
        const bool m0 = mkb[jl0] != 0;
        const bool m1 = mkb[jl0 + 1] != 0;
        float e0 = m0 ? 0.f : __expf(acc[t][0] + pos11);
        float e1 = m1 ? 0.f : __expf(acc[t][1] + pos12);
        float e2 = m0 ? 0.f : __expf(acc[t][2] + pos21);
        float e3 = m1 ? 0.f : __expf(acc[t][3] + pos22);
        acc[t][0] = e0; acc[t][1] = e1; acc[t][2] = e2; acc[t][3] = e3;
        s1 += e0 + e1;
        s2 += e2 + e3;
    }
    s1 += __shfl_xor_sync(0xffffffffu, s1, 1);
    s1 += __shfl_xor_sync(0xffffffffu, s1, 2);
    s2 += __shfl_xor_sync(0xffffffffu, s2, 1);
    s2 += __shfl_xor_sync(0xffffffffu, s2, 2);
    if (tig == 0) {
        red_s[r1*8 + pairid] = s1;
        red_s[r2*8 + pairid] = s2;
    }
    __syncthreads();
    if (tid < 32) {
        float s = red_s[tid*8];
#pragma unroll
        for (int i = 1; i < 8; ++i) s += red_s[tid*8 + i];
        inv_s[tid] = 1.0f / s;
    }
    __syncthreads();

    // ---- normalize + streaming store ----
    const float i1 = inv_s[r1], i2 = inv_s[r2];
    float* o1 = out + (hbSQ + q0 + r1)*SQ;
    float* o2 = out + (hbSQ + q0 + r2)*SQ;
#pragma unroll
    for (int t = 0; t < 16; ++t) {
        const int j0 = jstart + 8*t + 2*tig;
        __stcs(&o1[j0],     acc[t][0] * i1);
        __stcs(&o1[j0 + 1], acc[t][1] * i1);
        __stcs(&o2[j0],     acc[t][2] * i2);
        __stcs(&o2[j0 + 1], acc[t][3] * i2);
    }
}

// ---------------------------------------------------------------------------
extern "C" void kernel_launch(void* const* d_in, const int* in_sizes, int n_in,
                              void* d_out, int out_size)
{
    const float* x            = (const float*)d_in[0];          // (S,B,E)
    const float* pos_emb      = (const float*)d_in[1];          // (1,2S-1,PDIM)
    const unsigned char* kpm  = (const unsigned char*)d_in[2];  // (B,S) bool
    const float* in_proj_w    = (const float*)d_in[3];          // (544,512)
    const float* in_proj_b    = (const float*)d_in[4];          // (544,)
    const float* linear_pos_w = (const float*)d_in[5];          // (32,192)
    float* out = (float*)d_out;                                 // (H,B,S,S)

    static bool attr_set = false;
    if (!attr_set) {
        cudaFuncSetAttribute(attn_kernel,
                             cudaFuncAttributeMaxDynamicSharedMemorySize, SMEM_ATTN);
        cudaFuncSetAttribute(proj_mma_kernel,
                             cudaFuncAttributeMaxDynamicSharedMemorySize, SMEM_PROJ);
        attr_set = true;
    }

    split_prep_kernel<<<(XTOT + WTOT + 255)/256, 256>>>(x, in_proj_w);

    dim3 g1(9, 64);
    proj_mma_kernel<<<g1, 256, SMEM_PROJ>>>(in_proj_b);

    dim3 g2((NPOS + 255)/256, NH);
    pe_kernel<<<g2, 256>>>(pos_emb, linear_pos_w);

    dim3 g3(SQ/32, NH*NB);
    attn_kernel<<<g3, 512, SMEM_ATTN>>>(kpm, out);
}

// round 10
// speedup vs baseline: 1.9714x; 1.0484x over previous
#include <cuda_runtime.h>
#include <cuda_fp16.h>
#include <cuda_bf16.h>

#define SQ 1024
#define NB 8
#define NE 512
#define NH 8
#define QHD 32
#define PHD 4
#define PDIM 192
#define NPOS (2*SQ-1)   // 2047
#define INPROJ 544
#define MROWS (SQ*NB)   // 8192
#define K2E (NE/2)      // 256

typedef unsigned long long u64;
typedef unsigned int u32;

// bf16 mma m16n8k16, fp32 accumulate (in-place)
#define MMA16816(d, a0, a1, a2, a3, b0, b1) \
    asm("mma.sync.aligned.m16n8k16.row.col.f32.bf16.bf16.f32 " \
        "{%0,%1,%2,%3}, {%4,%5,%6,%7}, {%8,%9}, {%0,%1,%2,%3};" \
        : "+f"(d[0]), "+f"(d[1]), "+f"(d[2]), "+f"(d[3]) \
        : "r"(a0), "r"(a1), "r"(a2), "r"(a3), "r"(b0), "r"(b1))

#define CPA16(d, s) asm volatile("cp.async.cg.shared.global [%0], [%1], 16;" :: "r"(d), "l"(s))
#define CPA8(d, s)  asm volatile("cp.async.ca.shared.global [%0], [%1], 8;"  :: "r"(d), "l"(s))
#define CPA4(d, s)  asm volatile("cp.async.ca.shared.global [%0], [%1], 4;"  :: "r"(d), "l"(s))
#define CPA_COMMIT() asm volatile("cp.async.commit_group;")
#define CPA_WAIT0()  asm volatile("cp.async.wait_group 0;" ::: "memory")

// Scratch (device globals; no allocations allowed)
__device__ __align__(16) u32  g_xh[MROWS*K2E];     // x split hi [row][k2]
__device__ __align__(16) u32  g_xl[MROWS*K2E];
__device__ __align__(16) u32  g_whT[K2E*INPROJ];   // w split hi, transposed [k2][col]
__device__ __align__(16) u32  g_wlT[K2E*INPROJ];
__device__ __align__(16) u32  g_qh[NH*NB*SQ*16];   // [hb][s][perm(d2)] bf16x2 hi
__device__ __align__(16) u32  g_ql[NH*NB*SQ*16];   // (q arrays store PERMUTED d2)
__device__ __align__(16) u32  g_kh[NH*NB*SQ*16];   // [hb][s][d2] (unpermuted)
__device__ __align__(16) u32  g_kl[NH*NB*SQ*16];
__device__ __align__(16) float g_p[NH*NB*SQ*PHD];  // [hb][s][d] fp32
__device__ __align__(16) uint2 g_pe_h[NH*NPOS + 8];// [h][n]: 4 x fp16 (+pad)

// v0,v1 -> hi (bf16x2: lo-half=v0), lo = residual pair
__device__ __forceinline__ void split_pair(float c0, float c1, u32& hi, u32& lo)
{
    u32 h;
    asm("cvt.rn.bf16x2.f32 %0, %1, %2;" : "=r"(h) : "f"(c1), "f"(c0));
    float f0 = __uint_as_float(h << 16);
    float f1 = __uint_as_float(h & 0xffff0000u);
    float r0 = c0 - f0, r1 = c1 - f1;
    asm("cvt.rn.bf16x2.f32 %0, %1, %2;" : "=r"(lo) : "f"(r1), "f"(r0));
    hi = h;
}

// ---------------------------------------------------------------------------
// Kernel 0: split x and w into bf16 hi/lo pair arrays (w also transposed).
// ---------------------------------------------------------------------------
#define XTOT (MROWS*K2E)
#define WTOT (INPROJ*K2E)

__global__ __launch_bounds__(256) void split_prep_kernel(
    const float* __restrict__ x, const float* __restrict__ w)
{
    int idx = blockIdx.x * 256 + threadIdx.x;
    if (idx < XTOT) {
        int row = idx >> 8, k2 = idx & 255;
        float2 v = *(const float2*)&x[(size_t)row*NE + 2*k2];
        u32 hi, lo; split_pair(v.x, v.y, hi, lo);
        g_xh[idx] = hi; g_xl[idx] = lo;
    } else {
        int i = idx - XTOT;
        if (i < WTOT) {
            int k2 = i / INPROJ, col = i % INPROJ;
            float2 v = *(const float2*)&w[(size_t)col*NE + 2*k2];
            u32 hi, lo; split_pair(v.x, v.y, hi, lo);
            g_whT[(size_t)k2*INPROJ + col] = hi;
            g_wlT[(size_t)k2*INPROJ + col] = lo;
        }
    }
}

// ---------------------------------------------------------------------------
// Kernel 1: proj = x @ W^T + b via split-bf16 mma.sync (hh+hl+lh).
// q epilogue writes PERMUTED d2 position: pos = (d2&3)*4 + (d2>>2).
// ---------------------------------------------------------------------------
#define PA 20
#define PB 72
#define ST_A  2560
#define ST_B  1152
#define ST_SZ (2*ST_A + 2*ST_B)
#define SMEM_PROJ (2*ST_SZ*4)

__global__ __launch_bounds__(256, 2) void proj_mma_kernel(
    const float* __restrict__ bias)
{
    extern __shared__ u32 sm[];
    const int tid = threadIdx.x;
    const int w = tid >> 5, lane = tid & 31;
    const int g = lane >> 2, tig = lane & 3;
    const int warp_m = w >> 1, warp_n = w & 1;
    const int m0 = blockIdx.y * 128;
    const int n0 = blockIdx.x * 64;

    const int a_row = tid >> 1, a_half = tid & 1;
    const uint4* xh4 = (const uint4*)g_xh;
    const uint4* xl4 = (const uint4*)g_xl;
    const size_t a_base = ((size_t)(m0 + a_row)*K2E) >> 2;

    const int b_k2l = tid >> 4, b_colq = tid & 15;
    const bool b_valid = (n0 + b_colq*4) < INPROJ;

    uint4 pa_h0, pa_h1, pa_l0, pa_l1, pb_h, pb_l;
    {
        size_t ai = a_base + a_half*2;
        pa_h0 = __ldg(&xh4[ai]);   pa_h1 = __ldg(&xh4[ai+1]);
        pa_l0 = __ldg(&xl4[ai]);   pa_l1 = __ldg(&xl4[ai+1]);
        if (b_valid) {
            size_t bi = ((size_t)b_k2l*INPROJ + n0 + b_colq*4) >> 2;
            pb_h = __ldg(&((const uint4*)g_whT)[bi]);
            pb_l = __ldg(&((const uint4*)g_wlT)[bi]);
        } else {
            pb_h = make_uint4(0,0,0,0); pb_l = pb_h;
        }
    }

    float acc[2][4][4];
#pragma unroll
    for (int mt = 0; mt < 2; ++mt)
#pragma unroll
        for (int nt = 0; nt < 4; ++nt)
#pragma unroll
            for (int i = 0; i < 4; ++i) acc[mt][nt][i] = 0.f;

    for (int kc = 0; kc < 16; ++kc) {
        const int s = kc & 1;
        u32* Ah = sm + s*ST_SZ;
        u32* Al = Ah + ST_A;
        u32* Bh = Al + ST_A;
        u32* Bl = Bh + ST_B;
        *(uint4*)&Ah[a_row*PA + a_half*8]     = pa_h0;
        *(uint4*)&Ah[a_row*PA + a_half*8 + 4] = pa_h1;
        *(uint4*)&Al[a_row*PA + a_half*8]     = pa_l0;
        *(uint4*)&Al[a_row*PA + a_half*8 + 4] = pa_l1;
        *(uint4*)&Bh[b_k2l*PB + b_colq*4] = pb_h;
        *(uint4*)&Bl[b_k2l*PB + b_colq*4] = pb_l;
        __syncthreads();
        if (kc < 15) {
            size_t ai = a_base + (kc+1)*4 + a_half*2;
            pa_h0 = __ldg(&xh4[ai]);   pa_h1 = __ldg(&xh4[ai+1]);
            pa_l0 = __ldg(&xl4[ai]);   pa_l1 = __ldg(&xl4[ai+1]);
            if (b_valid) {
                size_t bi = ((size_t)((kc+1)*16 + b_k2l)*INPROJ + n0 + b_colq*4) >> 2;
                pb_h = __ldg(&((const uint4*)g_whT)[bi]);
                pb_l = __ldg(&((const uint4*)g_wlT)[bi]);
            }
        }
#pragma unroll
        for (int ks = 0; ks < 2; ++ks) {
            const int kb = ks*8;
            u32 ah[2][4], al[2][4];
#pragma unroll
            for (int mt = 0; mt < 2; ++mt) {
                int r1 = (warp_m*32 + mt*16 + g) * PA;
                int r2 = r1 + 8*PA;
                ah[mt][0] = Ah[r1 + kb + tig];
                ah[mt][1] = Ah[r2 + kb + tig];
                ah[mt][2] = Ah[r1 + kb + 4 + tig];
                ah[mt][3] = Ah[r2 + kb + 4 + tig];
                al[mt][0] = Al[r1 + kb + tig];
                al[mt][1] = Al[r2 + kb + tig];
                al[mt][2] = Al[r1 + kb + 4 + tig];
                al[mt][3] = Al[r2 + kb + 4 + tig];
            }
#pragma unroll
            for (int nt = 0; nt < 4; ++nt) {
                int col = warp_n*32 + nt*8 + g;
                u32 bh0 = Bh[(kb + tig)*PB + col];
                u32 bh1 = Bh[(kb + 4 + tig)*PB + col];
                u32 bl0 = Bl[(kb + tig)*PB + col];
                u32 bl1 = Bl[(kb + 4 + tig)*PB + col];
#pragma unroll
                for (int mt = 0; mt < 2; ++mt) {
                    MMA16816(acc[mt][nt], ah[mt][0], ah[mt][1], ah[mt][2], ah[mt][3], bh0, bh1);
                    MMA16816(acc[mt][nt], ah[mt][0], ah[mt][1], ah[mt][2], ah[mt][3], bl0, bl1);
                    MMA16816(acc[mt][nt], al[mt][0], al[mt][1], al[mt][2], al[mt][3], bh0, bh1);
                }
            }
        }
        __syncthreads();
    }

#pragma unroll
    for (int nt = 0; nt < 4; ++nt) {
        const int n = n0 + warp_n*32 + nt*8 + 2*tig;
        if (n >= INPROJ) continue;
        const float b0 = __ldg(&bias[n]);
        const float b1 = __ldg(&bias[n+1]);
#pragma unroll
        for (int mt = 0; mt < 2; ++mt) {
#pragma unroll
            for (int rr = 0; rr < 2; ++rr) {
                const int m = m0 + warp_m*32 + mt*16 + g + rr*8;
                const int srow = m >> 3, bb = m & 7;
                const float c0 = acc[mt][nt][2*rr]     + b0;
                const float c1 = acc[mt][nt][2*rr + 1] + b1;
                if (n < 512) {
                    int nn = n & 255;
                    int h = nn >> 5, d2 = (nn & 31) >> 1;
                    u32 hi, lo;
                    split_pair(c0, c1, hi, lo);
                    if (n < 256) {
                        int pos = (d2 & 3)*4 + (d2 >> 2);   // permuted for LDG.128 A-frags
                        size_t off = (((size_t)(h*8+bb))*SQ + srow)*16 + pos;
                        g_qh[off] = hi; g_ql[off] = lo;
                    } else {
                        size_t off = (((size_t)(h*8+bb))*SQ + srow)*16 + d2;
                        g_kh[off] = hi; g_kl[off] = lo;
                    }
                } else {
                    int n3 = n - 512;
                    int h = n3 >> 2, d = n3 & 3;
                    size_t off = (((size_t)(h*8+bb))*SQ + srow)*PHD + d;
                    g_p[off]   = c0;
                    g_p[off+1] = c1;
                }
            }
        }
    }
}

// ---------------------------------------------------------------------------
// Kernel 2: g_pe_h[h][n] = fp16x4 of sum_p pos_emb[n][p] * lw[h*4+d][p]
// ---------------------------------------------------------------------------
__global__ __launch_bounds__(256) void pe_kernel(
    const float* __restrict__ pos_emb, const float* __restrict__ lw)
{
    __shared__ float ws[4][193];
    const int tid = threadIdx.x;
    const int h = blockIdx.y;
    for (int i = tid; i < 4*PDIM; i += 256) {
        int o = i / PDIM, p = i % PDIM;
        ws[o][p] = lw[(h*4+o)*PDIM + p];
    }
    __syncthreads();
    int n = blockIdx.x * 256 + tid;
    if (n >= NPOS) return;
    float a0 = 0.f, a1 = 0.f, a2 = 0.f, a3 = 0.f;
    const float4* pr = (const float4*)&pos_emb[(size_t)n*PDIM];
#pragma unroll 4
    for (int p4 = 0; p4 < PDIM/4; ++p4) {
        float4 pv = __ldg(&pr[p4]);
        int p = p4*4;
        a0 = fmaf(pv.x, ws[0][p+0], a0); a1 = fmaf(pv.x, ws[1][p+0], a1);
        a2 = fmaf(pv.x, ws[2][p+0], a2); a3 = fmaf(pv.x, ws[3][p+0], a3);
        a0 = fmaf(pv.y, ws[0][p+1], a0); a1 = fmaf(pv.y, ws[1][p+1], a1);
        a2 = fmaf(pv.y, ws[2][p+1], a2); a3 = fmaf(pv.y, ws[3][p+1], a3);
        a0 = fmaf(pv.z, ws[0][p+2], a0); a1 = fmaf(pv.z, ws[1][p+2], a1);
        a2 = fmaf(pv.z, ws[2][p+2], a2); a3 = fmaf(pv.z, ws[3][p+2], a3);
        a0 = fmaf(pv.w, ws[0][p+3], a0); a1 = fmaf(pv.w, ws[1][p+3], a1);
        a2 = fmaf(pv.w, ws[2][p+3], a2); a3 = fmaf(pv.w, ws[3][p+3], a3);
    }
    __half2 h01 = __floats2half2_rn(a0, a1);
    __half2 h23 = __floats2half2_rn(a2, a3);
    g_pe_h[h*NPOS + n] = make_uint2(*(unsigned*)&h01, *(unsigned*)&h23);
}

// ---------------------------------------------------------------------------
// Kernel 3: tensor-core scores + rel-shift + mask + softmax.
// Fused software-pipelined loop: LDS B(t) prefetched, MMA(t), epilogue(t-1).
// A-frags via 4x LDG.128 (permuted q layout), issued before cp.async wait.
// ---------------------------------------------------------------------------
#define KJ_P 20
#define OFF_KB   0                         // 2 * 1024*20*4 = 163840
#define KB_LO    (1024*KJ_P)               // u32 offset of lo array
#define OFF_PEL  163840                    // 8 pairs * 160 uint2 = 10240
#define OFF_RED  174080                    // 32*8*4 = 1024
#define OFF_INV  175104                    // 128
#define OFF_MASK 175232                    // 8 pairs * 128 = 1024
#define SMEM_ATTN 176256

struct BFrag { u32 h0, h1, h2, h3, l0, l1, l2, l3; };

__device__ __forceinline__ void ld_bfrag(BFrag& f, const u32* kb2h, const u32* kb2l,
                                         int jc, int tig)
{
    const u32* kr = kb2h + jc*KJ_P;
    const u32* lr = kb2l + jc*KJ_P;
    f.h0 = kr[tig];     f.h1 = kr[4 + tig];
    f.h2 = kr[8 + tig]; f.h3 = kr[12 + tig];
    f.l0 = lr[tig];     f.l1 = lr[4 + tig];
    f.l2 = lr[8 + tig]; f.l3 = lr[12 + tig];
}

__global__ __launch_bounds__(512, 1) void attn_kernel(
    const unsigned char* __restrict__ kpm, float* __restrict__ out)
{
    extern __shared__ char smraw[];
    u32*   kb2h  = (u32*)(smraw + OFF_KB);       // [1024 j][20] (16 k2 used)
    u32*   kb2l  = kb2h + KB_LO;
    uint2* pe_l  = (uint2*)(smraw + OFF_PEL);    // [8 pairs][160]
    float* red_s = (float*)(smraw + OFF_RED);    // [32][8]
    float* inv_s = (float*)(smraw + OFF_INV);    // [32]
    unsigned char* mask_l = (unsigned char*)(smraw + OFF_MASK); // [8][128]
    const u32 smb = (u32)__cvta_generic_to_shared(smraw);

    const int tid = threadIdx.x;
    const int w = tid >> 5, lane = tid & 31;
    const int g = lane >> 2, tig = lane & 3;
    const int pairid = w >> 1;
    const int jstart = pairid * 128;
    const int hb = blockIdx.y;
    const int h = hb >> 3, b = hb & 7;
    const int q0 = blockIdx.x * 32;
    const size_t hbSQ = (size_t)hb * SQ;

    // ---- per-pair async fills ----
    {   // K span: even warp copies hi, odd copies lo (128 j rows x 64B)
        const u32* ksrc = ((w & 1) ? g_kl : g_kh) + (hbSQ + jstart)*16;
        const u32 kdst = smb + OFF_KB + (w & 1)*(KB_LO*4) + jstart*KJ_P*4;
#pragma unroll
        for (int i = 0; i < 16; ++i) {
            int lin = i*32 + lane;
            int jl = lin >> 2, seg = lin & 3;
            CPA16(kdst + (jl*KJ_P + seg*4)*4, ksrc + jl*16 + seg*4);
        }
        const uint2* pesrc = g_pe_h + h*NPOS + (992 - q0) + jstart;
        const u32 pedst = smb + OFF_PEL + pairid*160*8;
        const int tpair = (w & 1)*32 + lane;
#pragma unroll
        for (int it = 0; it < 3; ++it) {
            int i = tpair + it*64;
            if (i < 160) CPA8(pedst + i*8, pesrc + i);
        }
        if (tpair < 32)
            CPA4(smb + OFF_MASK + pairid*128 + tpair*4,
                 kpm + (size_t)b*SQ + jstart + tpair*4);
        CPA_COMMIT();
    }

    const int rbase = (w & 1) * 16;
    const int r1 = rbase + g, r2 = r1 + 8;

    // ---- A fragments: 4x LDG.128 (permuted layout), before the wait ----
    u32 ah[8], al[8];
    {
        const uint4* qa = (const uint4*)(g_qh + (hbSQ + q0 + r1)*16);
        const uint4* qb = (const uint4*)(g_qh + (hbSQ + q0 + r2)*16);
        const uint4* la = (const uint4*)(g_ql + (hbSQ + q0 + r1)*16);
        const uint4* lb = (const uint4*)(g_ql + (hbSQ + q0 + r2)*16);
        uint4 v1 = __ldg(&qa[tig]);
        uint4 v2 = __ldg(&qb[tig]);
        uint4 u1 = __ldg(&la[tig]);
        uint4 u2 = __ldg(&lb[tig]);
        ah[0] = v1.x; ah[1] = v2.x; ah[2] = v1.y; ah[3] = v2.y;
        ah[4] = v1.z; ah[5] = v2.z; ah[6] = v1.w; ah[7] = v2.w;
        al[0] = u1.x; al[1] = u2.x; al[2] = u1.y; al[3] = u2.y;
        al[4] = u1.z; al[5] = u2.z; al[6] = u1.w; al[7] = u2.w;
    }
    // ---- p rows (fp32 -> fp16x2 pairs) ----
    __half2 p1a, p1b, p2a, p2b;
    {
        float4 pv1 = *(const float4*)(g_p + (hbSQ + q0 + r1)*PHD);
        float4 pv2 = *(const float4*)(g_p + (hbSQ + q0 + r2)*PHD);
        p1a = __floats2half2_rn(pv1.x, pv1.y);
        p1b = __floats2half2_rn(pv1.z, pv1.w);
        p2a = __floats2half2_rn(pv2.x, pv2.y);
        p2b = __floats2half2_rn(pv2.z, pv2.w);
    }

    CPA_WAIT0();
    asm volatile("bar.sync %0, 64;" :: "r"(1 + pairid) : "memory");

    float acc[16][4];
#pragma unroll
    for (int t = 0; t < 16; ++t)
#pragma unroll
        for (int i = 0; i < 4; ++i) acc[t][i] = 0.f;

    const uint2* peb = pe_l + pairid*160;
    const unsigned char* mkb = mask_l + pairid*128;
    float s1 = 0.f, s2 = 0.f;

    // ---- fused pipelined loop: MMA(t) overlaps epilogue(t-1) ----
    BFrag bf;
    ld_bfrag(bf, kb2h, kb2l, jstart + g, tig);
#pragma unroll
    for (int t = 0; t < 16; ++t) {
        BFrag cur = bf;
        if (t < 15) ld_bfrag(bf, kb2h, kb2l, jstart + 8*(t+1) + g, tig);
        MMA16816(acc[t], ah[0], ah[1], ah[2], ah[3], cur.h0, cur.h1);
        MMA16816(acc[t], ah[4], ah[5], ah[6], ah[7], cur.h2, cur.h3);
        MMA16816(acc[t], ah[0], ah[1], ah[2], ah[3], cur.l0, cur.l1);
        MMA16816(acc[t], ah[4], ah[5], ah[6], ah[7], cur.l2, cur.l3);
        MMA16816(acc[t], al[0], al[1], al[2], al[3], cur.h0, cur.h1);
        MMA16816(acc[t], al[4], al[5], al[6], al[7], cur.h2, cur.h3);

        if (t > 0) {
            const int e = t - 1;
            const int jl0 = 8*e + 2*tig;
            const int idx1 = jl0 + 31 - r1;
            const int idx2 = idx1 - 8;
            uint2 e11 = peb[idx1];
            uint2 e12 = peb[idx1 + 1];
            uint2 e21 = peb[idx2];
            uint2 e22 = peb[idx2 + 1];
            __half2 q11 = __hfma2(p1a, *(__half2*)&e11.x, __hmul2(p1b, *(__half2*)&e11.y));
            __half2 q12 = __hfma2(p1a, *(__half2*)&e12.x, __hmul2(p1b, *(__half2*)&e12.y));
            __half2 q21 = __hfma2(p2a, *(__half2*)&e21.x, __hmul2(p2b, *(__half2*)&e21.y));
            __half2 q22 = __hfma2(p2a, *(__half2*)&e22.x, __hmul2(p2b, *(__half2*)&e22.y));
            const bool m0 = mkb[jl0] != 0;
            const bool m1 = mkb[jl0 + 1] != 0;
            float e0 = m0 ? 0.f : __expf(acc[e][0] + __low2float(q11) + __high2float(q11));
            float e1 = m1 ? 0.f : __expf(acc[e][1] + __low2float(q12) + __high2float(q12));
            float e2 = m0 ? 0.f : __expf(acc[e][2] + __low2float(q21) + __high2float(q21));
            float e3 = m1 ? 0.f : __expf(acc[e][3] + __low2float(q22) + __high2float(q22));
            acc[e][0] = e0; acc[e][1] = e1; acc[e][2] = e2; acc[e][3] = e3;
            s1 += e0 + e1;
            s2 += e2 + e3;
        }
    }
    {   // epilogue tile 15
        const int e = 15;
        const int jl0 = 8*e + 2*tig;
        const int idx1 = jl0 + 31 - r1;
        const int idx2 = idx1 - 8;
        uint2 e11 = peb[idx1];
        uint2 e12 = peb[idx1 + 1];
        uint2 e21 = peb[idx2];
        uint2 e22 = peb[idx2 + 1];
        __half2 q11 = __hfma2(p1a, *(__half2*)&e11.x, __hmul2(p1b, *(__half2*)&e11.y));
        __half2 q12 = __hfma2(p1a, *(__half2*)&e12.x, __hmul2(p1b, *(__half2*)&e12.y));
        __half2 q21 = __hfma2(p2a, *(__half2*)&e21.x, __hmul2(p2b, *(__half2*)&e21.y));
        __half2 q22 = __hfma2(p2a, *(__half2*)&e22.x, __hmul2(p2b, *(__half2*)&e22.y));
        const bool m0 = mkb[jl0] != 0;
        const bool m1 = mkb[jl0 + 1] != 0;
        float e0 = m0 ? 0.f : __expf(acc[e][0] + __low2float(q11) + __high2float(q11));
        float e1 = m1 ? 0.f : __expf(acc[e][1] + __low2float(q12) + __high2float(q12));
        float e2 = m0 ? 0.f : __expf(acc[e][2] + __low2float(q21) + __high2float(q21));
        float e3 = m1 ? 0.f : __expf(acc[e][3] + __low2float(q22) + __high2float(q22));
        acc[e][0] = e0; acc[e][1] = e1; acc[e][2] = e2; acc[e][3] = e3;
        s1 += e0 + e1;
        s2 += e2 + e3;
    }

    s1 += __shfl_xor_sync(0xffffffffu, s1, 1);
    s1 += __shfl_xor_sync(0xffffffffu, s1, 2);
    s2 += __shfl_xor_sync(0xffffffffu, s2, 1);
    s2 += __shfl_xor_sync(0xffffffffu, s2, 2);
    if (tig == 0) {
        red_s[r1*8 + pairid] = s1;
        red_s[r2*8 + pairid] = s2;
    }
    __syncthreads();
    if (tid < 32) {
        float s = red_s[tid*8];
#pragma unroll
        for (int i = 1; i < 8; ++i) s += red_s[tid*8 + i];
        inv_s[tid] = 1.0f / s;
    }
    __syncthreads();

    // ---- normalize + streaming float2 stores ----
    const float i1 = inv_s[r1], i2 = inv_s[r2];
    float2* o1 = (float2*)(out + (hbSQ + q0 + r1)*SQ);
    float2* o2 = (float2*)(out + (hbSQ + q0 + r2)*SQ);
#pragma unroll
    for (int t = 0; t < 16; ++t) {
        const int jp = (jstart + 8*t + 2*tig) >> 1;
        float2 v1 = make_float2(acc[t][0] * i1, acc[t][1] * i1);
        float2 v2 = make_float2(acc[t][2] * i2, acc[t][3] * i2);
        __stcs(&o1[jp], v1);
        __stcs(&o2[jp], v2);
    }
}

// ---------------------------------------------------------------------------
extern "C" void kernel_launch(void* const* d_in, const int* in_sizes, int n_in,
                              void* d_out, int out_size)
{
    const float* x            = (const float*)d_in[0];          // (S,B,E)
    const float* pos_emb      = (const float*)d_in[1];          // (1,2S-1,PDIM)
    const unsigned char* kpm  = (const unsigned char*)d_in[2];  // (B,S) bool
    const float* in_proj_w    = (const float*)d_in[3];          // (544,512)
    const float* in_proj_b    = (const float*)d_in[4];          // (544,)
    const float* linear_pos_w = (const float*)d_in[5];          // (32,192)
    float* out = (float*)d_out;                                 // (H,B,S,S)

    static bool attr_set = false;
    if (!attr_set) {
        cudaFuncSetAttribute(attn_kernel,
                             cudaFuncAttributeMaxDynamicSharedMemorySize, SMEM_ATTN);
        cudaFuncSetAttribute(proj_mma_kernel,
                             cudaFuncAttributeMaxDynamicSharedMemorySize, SMEM_PROJ);
        attr_set = true;
    }

    split_prep_kernel<<<(XTOT + WTOT + 255)/256, 256>>>(x, in_proj_w);

    dim3 g1(9, 64);
    proj_mma_kernel<<<g1, 256, SMEM_PROJ>>>(in_proj_b);

    dim3 g2((NPOS + 255)/256, NH);
    pe_kernel<<<g2, 256>>>(pos_emb, linear_pos_w);

    dim3 g3(SQ/32, NH*NB);
    attn_kernel<<<g3, 512, SMEM_ATTN>>>(kpm, out);
}

// round 11
// speedup vs baseline: 2.1159x; 1.0733x over previous
#include <cuda_runtime.h>
#include <cuda_fp16.h>
#include <cuda_bf16.h>

#define SQ 1024
#define NB 8
#define NE 512
#define NH 8
#define QHD 32
#define PHD 4
#define PDIM 192
#define NPOS (2*SQ-1)   // 2047
#define INPROJ 544
#define MROWS (SQ*NB)   // 8192
#define K2E (NE/2)      // 256

typedef unsigned long long u64;
typedef unsigned int u32;

// bf16 mma m16n8k16, fp32 accumulate (in-place)
#define MMA16816(d, a0, a1, a2, a3, b0, b1) \
    asm("mma.sync.aligned.m16n8k16.row.col.f32.bf16.bf16.f32 " \
        "{%0,%1,%2,%3}, {%4,%5,%6,%7}, {%8,%9}, {%0,%1,%2,%3};" \
        : "+f"(d[0]), "+f"(d[1]), "+f"(d[2]), "+f"(d[3]) \
        : "r"(a0), "r"(a1), "r"(a2), "r"(a3), "r"(b0), "r"(b1))

#define CPA16(d, s) asm volatile("cp.async.cg.shared.global [%0], [%1], 16;" :: "r"(d), "l"(s))
#define CPA8(d, s)  asm volatile("cp.async.ca.shared.global [%0], [%1], 8;"  :: "r"(d), "l"(s))
#define CPA4(d, s)  asm volatile("cp.async.ca.shared.global [%0], [%1], 4;"  :: "r"(d), "l"(s))
#define CPA_COMMIT() asm volatile("cp.async.commit_group;")
#define CPA_WAITG1() asm volatile("cp.async.wait_group 1;" ::: "memory")

// Scratch (device globals; no allocations allowed)
__device__ __align__(16) u32  g_xh[MROWS*K2E];     // x split hi [row][k2]
__device__ __align__(16) u32  g_xl[MROWS*K2E];
__device__ __align__(16) u32  g_whT[K2E*INPROJ];   // w split hi, transposed [k2][col]
__device__ __align__(16) u32  g_wlT[K2E*INPROJ];
__device__ __align__(16) u32  g_qh[NH*NB*SQ*16];   // [hb][s][perm(d2)] bf16x2 hi
__device__ __align__(16) u32  g_ql[NH*NB*SQ*16];   // (q arrays store PERMUTED d2)
__device__ __align__(16) u32  g_kh[NH*NB*SQ*16];   // [hb][s][d2] (unpermuted)
__device__ __align__(16) u32  g_kl[NH*NB*SQ*16];
__device__ __align__(16) float g_p[NH*NB*SQ*PHD];  // [hb][s][d] fp32
__device__ __align__(16) uint2 g_pe_h[NH*NPOS + 8];// [h][n]: 4 x fp16 (+pad)

// v0,v1 -> hi (bf16x2: lo-half=v0), lo = residual pair
__device__ __forceinline__ void split_pair(float c0, float c1, u32& hi, u32& lo)
{
    u32 h;
    asm("cvt.rn.bf16x2.f32 %0, %1, %2;" : "=r"(h) : "f"(c1), "f"(c0));
    float f0 = __uint_as_float(h << 16);
    float f1 = __uint_as_float(h & 0xffff0000u);
    float r0 = c0 - f0, r1 = c1 - f1;
    asm("cvt.rn.bf16x2.f32 %0, %1, %2;" : "=r"(lo) : "f"(r1), "f"(r0));
    hi = h;
}

// ---------------------------------------------------------------------------
// Kernel 0: split x and w into bf16 hi/lo pair arrays (w also transposed).
// ---------------------------------------------------------------------------
#define XTOT (MROWS*K2E)
#define WTOT (INPROJ*K2E)

__global__ __launch_bounds__(256) void split_prep_kernel(
    const float* __restrict__ x, const float* __restrict__ w)
{
    int idx = blockIdx.x * 256 + threadIdx.x;
    if (idx < XTOT) {
        int row = idx >> 8, k2 = idx & 255;
        float2 v = *(const float2*)&x[(size_t)row*NE + 2*k2];
        u32 hi, lo; split_pair(v.x, v.y, hi, lo);
        g_xh[idx] = hi; g_xl[idx] = lo;
    } else {
        int i = idx - XTOT;
        if (i < WTOT) {
            int k2 = i / INPROJ, col = i % INPROJ;
            float2 v = *(const float2*)&w[(size_t)col*NE + 2*k2];
            u32 hi, lo; split_pair(v.x, v.y, hi, lo);
            g_whT[(size_t)k2*INPROJ + col] = hi;
            g_wlT[(size_t)k2*INPROJ + col] = lo;
        }
    }
}

// ---------------------------------------------------------------------------
// Kernel 1: proj = x @ W^T + b via split-bf16 mma.sync (hh+hl+lh).
// q epilogue writes PERMUTED d2 position: pos = (d2&3)*4 + (d2>>2).
// ---------------------------------------------------------------------------
#define PA 20
#define PB 72
#define ST_A  2560
#define ST_B  1152
#define ST_SZ (2*ST_A + 2*ST_B)
#define SMEM_PROJ (2*ST_SZ*4)

__global__ __launch_bounds__(256, 2) void proj_mma_kernel(
    const float* __restrict__ bias)
{
    extern __shared__ u32 sm[];
    const int tid = threadIdx.x;
    const int w = tid >> 5, lane = tid & 31;
    const int g = lane >> 2, tig = lane & 3;
    const int warp_m = w >> 1, warp_n = w & 1;
    const int m0 = blockIdx.y * 128;
    const int n0 = blockIdx.x * 64;

    const int a_row = tid >> 1, a_half = tid & 1;
    const uint4* xh4 = (const uint4*)g_xh;
    const uint4* xl4 = (const uint4*)g_xl;
    const size_t a_base = ((size_t)(m0 + a_row)*K2E) >> 2;

    const int b_k2l = tid >> 4, b_colq = tid & 15;
    const bool b_valid = (n0 + b_colq*4) < INPROJ;

    uint4 pa_h0, pa_h1, pa_l0, pa_l1, pb_h, pb_l;
    {
        size_t ai = a_base + a_half*2;
        pa_h0 = __ldg(&xh4[ai]);   pa_h1 = __ldg(&xh4[ai+1]);
        pa_l0 = __ldg(&xl4[ai]);   pa_l1 = __ldg(&xl4[ai+1]);
        if (b_valid) {
            size_t bi = ((size_t)b_k2l*INPROJ + n0 + b_colq*4) >> 2;
            pb_h = __ldg(&((const uint4*)g_whT)[bi]);
            pb_l = __ldg(&((const uint4*)g_wlT)[bi]);
        } else {
            pb_h = make_uint4(0,0,0,0); pb_l = pb_h;
        }
    }

    float acc[2][4][4];
#pragma unroll
    for (int mt = 0; mt < 2; ++mt)
#pragma unroll
        for (int nt = 0; nt < 4; ++nt)
#pragma unroll
            for (int i = 0; i < 4; ++i) acc[mt][nt][i] = 0.f;

    for (int kc = 0; kc < 16; ++kc) {
        const int s = kc & 1;
        u32* Ah = sm + s*ST_SZ;
        u32* Al = Ah + ST_A;
        u32* Bh = Al + ST_A;
        u32* Bl = Bh + ST_B;
        *(uint4*)&Ah[a_row*PA + a_half*8]     = pa_h0;
        *(uint4*)&Ah[a_row*PA + a_half*8 + 4] = pa_h1;
        *(uint4*)&Al[a_row*PA + a_half*8]     = pa_l0;
        *(uint4*)&Al[a_row*PA + a_half*8 + 4] = pa_l1;
        *(uint4*)&Bh[b_k2l*PB + b_colq*4] = pb_h;
        *(uint4*)&Bl[b_k2l*PB + b_colq*4] = pb_l;
        __syncthreads();
        if (kc < 15) {
            size_t ai = a_base + (kc+1)*4 + a_half*2;
            pa_h0 = __ldg(&xh4[ai]);   pa_h1 = __ldg(&xh4[ai+1]);
            pa_l0 = __ldg(&xl4[ai]);   pa_l1 = __ldg(&xl4[ai+1]);
            if (b_valid) {
                size_t bi = ((size_t)((kc+1)*16 + b_k2l)*INPROJ + n0 + b_colq*4) >> 2;
                pb_h = __ldg(&((const uint4*)g_whT)[bi]);
                pb_l = __ldg(&((const uint4*)g_wlT)[bi]);
            }
        }
#pragma unroll
        for (int ks = 0; ks < 2; ++ks) {
            const int kb = ks*8;
            u32 ah[2][4], al[2][4];
#pragma unroll
            for (int mt = 0; mt < 2; ++mt) {
                int r1 = (warp_m*32 + mt*16 + g) * PA;
                int r2 = r1 + 8*PA;
                ah[mt][0] = Ah[r1 + kb + tig];
                ah[mt][1] = Ah[r2 + kb + tig];
                ah[mt][2] = Ah[r1 + kb + 4 + tig];
                ah[mt][3] = Ah[r2 + kb + 4 + tig];
                al[mt][0] = Al[r1 + kb + tig];
                al[mt][1] = Al[r2 + kb + tig];
                al[mt][2] = Al[r1 + kb + 4 + tig];
                al[mt][3] = Al[r2 + kb + 4 + tig];
            }
#pragma unroll
            for (int nt = 0; nt < 4; ++nt) {
                int col = warp_n*32 + nt*8 + g;
                u32 bh0 = Bh[(kb + tig)*PB + col];
                u32 bh1 = Bh[(kb + 4 + tig)*PB + col];
                u32 bl0 = Bl[(kb + tig)*PB + col];
                u32 bl1 = Bl[(kb + 4 + tig)*PB + col];
#pragma unroll
                for (int mt = 0; mt < 2; ++mt) {
                    MMA16816(acc[mt][nt], ah[mt][0], ah[mt][1], ah[mt][2], ah[mt][3], bh0, bh1);
                    MMA16816(acc[mt][nt], ah[mt][0], ah[mt][1], ah[mt][2], ah[mt][3], bl0, bl1);
                    MMA16816(acc[mt][nt], al[mt][0], al[mt][1], al[mt][2], al[mt][3], bh0, bh1);
                }
            }
        }
        __syncthreads();
    }

#pragma unroll
    for (int nt = 0; nt < 4; ++nt) {
        const int n = n0 + warp_n*32 + nt*8 + 2*tig;
        if (n >= INPROJ) continue;
        const float b0 = __ldg(&bias[n]);
        const float b1 = __ldg(&bias[n+1]);
#pragma unroll
        for (int mt = 0; mt < 2; ++mt) {
#pragma unroll
            for (int rr = 0; rr < 2; ++rr) {
                const int m = m0 + warp_m*32 + mt*16 + g + rr*8;
                const int srow = m >> 3, bb = m & 7;
                const float c0 = acc[mt][nt][2*rr]     + b0;
                const float c1 = acc[mt][nt][2*rr + 1] + b1;
                if (n < 512) {
                    int nn = n & 255;
                    int h = nn >> 5, d2 = (nn & 31) >> 1;
                    u32 hi, lo;
                    split_pair(c0, c1, hi, lo);
                    if (n < 256) {
                        int pos = (d2 & 3)*4 + (d2 >> 2);   // permuted for LDG.128 A-frags
                        size_t off = (((size_t)(h*8+bb))*SQ + srow)*16 + pos;
                        g_qh[off] = hi; g_ql[off] = lo;
                    } else {
                        size_t off = (((size_t)(h*8+bb))*SQ + srow)*16 + d2;
                        g_kh[off] = hi; g_kl[off] = lo;
                    }
                } else {
                    int n3 = n - 512;
                    int h = n3 >> 2, d = n3 & 3;
                    size_t off = (((size_t)(h*8+bb))*SQ + srow)*PHD + d;
                    g_p[off]   = c0;
                    g_p[off+1] = c1;
                }
            }
        }
    }
}

// ---------------------------------------------------------------------------
// Kernel 2: g_pe_h[h][n] = fp16x4 of sum_p pos_emb[n][p] * lw[h*4+d][p]
// ---------------------------------------------------------------------------
__global__ __launch_bounds__(256) void pe_kernel(
    const float* __restrict__ pos_emb, const float* __restrict__ lw)
{
    __shared__ float ws[4][193];
    const int tid = threadIdx.x;
    const int h = blockIdx.y;
    for (int i = tid; i < 4*PDIM; i += 256) {
        int o = i / PDIM, p = i % PDIM;
        ws[o][p] = lw[(h*4+o)*PDIM + p];
    }
    __syncthreads();
    int n = blockIdx.x * 256 + tid;
    if (n >= NPOS) return;
    float a0 = 0.f, a1 = 0.f, a2 = 0.f, a3 = 0.f;
    const float4* pr = (const float4*)&pos_emb[(size_t)n*PDIM];
#pragma unroll 4
    for (int p4 = 0; p4 < PDIM/4; ++p4) {
        float4 pv = __ldg(&pr[p4]);
        int p = p4*4;
        a0 = fmaf(pv.x, ws[0][p+0], a0); a1 = fmaf(pv.x, ws[1][p+0], a1);
        a2 = fmaf(pv.x, ws[2][p+0], a2); a3 = fmaf(pv.x, ws[3][p+0], a3);
        a0 = fmaf(pv.y, ws[0][p+1], a0); a1 = fmaf(pv.y, ws[1][p+1], a1);
        a2 = fmaf(pv.y, ws[2][p+1], a2); a3 = fmaf(pv.y, ws[3][p+1], a3);
        a0 = fmaf(pv.z, ws[0][p+2], a0); a1 = fmaf(pv.z, ws[1][p+2], a1);
        a2 = fmaf(pv.z, ws[2][p+2], a2); a3 = fmaf(pv.z, ws[3][p+2], a3);
        a0 = fmaf(pv.w, ws[0][p+3], a0); a1 = fmaf(pv.w, ws[1][p+3], a1);
        a2 = fmaf(pv.w, ws[2][p+3], a2); a3 = fmaf(pv.w, ws[3][p+3], a3);
    }
    __half2 h01 = __floats2half2_rn(a0, a1);
    __half2 h23 = __floats2half2_rn(a2, a3);
    g_pe_h[h*NPOS + n] = make_uint2(*(unsigned*)&h01, *(unsigned*)&h23);
}

// ---------------------------------------------------------------------------
// Kernel 3: persistent attention. Grid (2, 64) = 128 CTAs, one per SM.
// Each CTA: one hb, K panel loaded ONCE into smem, 16 q-tile iterations with
// pe double-buffered cp.async and A/p register prefetch.
// ---------------------------------------------------------------------------
#define KJ_P 20
#define OFF_KB   0                          // 2 * 1024*20*4 = 163840
#define KB_LO    (1024*KJ_P)                // u32 offset of lo array
#define OFF_PE0  163840                     // 8 pairs * 160 uint2 = 10240
#define OFF_PE1  174080                     // 10240
#define OFF_RED  184320                     // 32*8*4 = 1024
#define OFF_INV  185344                     // 128
#define OFF_MASK 185472                     // 8 pairs * 128 = 1024
#define SMEM_ATTN 186496

struct BFrag { u32 h0, h1, h2, h3, l0, l1, l2, l3; };

__device__ __forceinline__ void ld_bfrag(BFrag& f, const u32* kb2h, const u32* kb2l,
                                         int jc, int tig)
{
    const u32* kr = kb2h + jc*KJ_P;
    const u32* lr = kb2l + jc*KJ_P;
    f.h0 = kr[tig];     f.h1 = kr[4 + tig];
    f.h2 = kr[8 + tig]; f.h3 = kr[12 + tig];
    f.l0 = lr[tig];     f.l1 = lr[4 + tig];
    f.l2 = lr[8 + tig]; f.l3 = lr[12 + tig];
}

__global__ __launch_bounds__(512, 1) void attn_kernel(
    const unsigned char* __restrict__ kpm, float* __restrict__ out)
{
    extern __shared__ char smraw[];
    u32*   kb2h  = (u32*)(smraw + OFF_KB);       // [1024 j][20] (16 k2 used)
    u32*   kb2l  = kb2h + KB_LO;
    float* red_s = (float*)(smraw + OFF_RED);    // [32][8]
    float* inv_s = (float*)(smraw + OFF_INV);    // [32]
    unsigned char* mask_l = (unsigned char*)(smraw + OFF_MASK); // [8][128]
    const u32 smb = (u32)__cvta_generic_to_shared(smraw);

    const int tid = threadIdx.x;
    const int w = tid >> 5, lane = tid & 31;
    const int g = lane >> 2, tig = lane & 3;
    const int pairid = w >> 1;
    const int jstart = pairid * 128;
    const int hb = blockIdx.y;
    const int h = hb >> 3, b = hb & 7;
    const int qbase = blockIdx.x * 512;
    const size_t hbSQ = (size_t)hb * SQ;
    const int tpair = (w & 1)*32 + lane;

    const int rbase = (w & 1) * 16;
    const int r1 = rbase + g, r2 = r1 + 8;

    // ---- prologue: K panel (once), mask (once), pe(0); A(0)/p(0) via LDG ----
    {
        const u32* ksrc = ((w & 1) ? g_kl : g_kh) + (hbSQ + jstart)*16;
        const u32 kdst = smb + OFF_KB + (w & 1)*(KB_LO*4) + jstart*KJ_P*4;
#pragma unroll
        for (int i = 0; i < 16; ++i) {
            int lin = i*32 + lane;
            int jl = lin >> 2, seg = lin & 3;
            CPA16(kdst + (jl*KJ_P + seg*4)*4, ksrc + jl*16 + seg*4);
        }
        if (tpair < 32)
            CPA4(smb + OFF_MASK + pairid*128 + tpair*4,
                 kpm + (size_t)b*SQ + jstart + tpair*4);
        // pe(0): window for q0 = qbase
        const uint2* pesrc = g_pe_h + h*NPOS + (992 - qbase) + jstart;
        const u32 pedst = smb + OFF_PE0 + pairid*160*8;
#pragma unroll
        for (int it = 0; it < 3; ++it) {
            int i = tpair + it*64;
            if (i < 160) CPA8(pedst + i*8, pesrc + i);
        }
        CPA_COMMIT();
    }

    // A(0)/p(0) prefetch (register, per-warp)
    u32 ah[8], al[8];
    float4 pv1, pv2;
    {
        const uint4* qa = (const uint4*)(g_qh + (hbSQ + qbase + r1)*16);
        const uint4* qb = (const uint4*)(g_qh + (hbSQ + qbase + r2)*16);
        const uint4* la = (const uint4*)(g_ql + (hbSQ + qbase + r1)*16);
        const uint4* lb = (const uint4*)(g_ql + (hbSQ + qbase + r2)*16);
        uint4 v1 = __ldg(&qa[tig]);
        uint4 v2 = __ldg(&qb[tig]);
        uint4 u1 = __ldg(&la[tig]);
        uint4 u2 = __ldg(&lb[tig]);
        ah[0] = v1.x; ah[1] = v2.x; ah[2] = v1.y; ah[3] = v2.y;
        ah[4] = v1.z; ah[5] = v2.z; ah[6] = v1.w; ah[7] = v2.w;
        al[0] = u1.x; al[1] = u2.x; al[2] = u1.y; al[3] = u2.y;
        al[4] = u1.z; al[5] = u2.z; al[6] = u1.w; al[7] = u2.w;
        pv1 = *(const float4*)(g_p + (hbSQ + qbase + r1)*PHD);
        pv2 = *(const float4*)(g_p + (hbSQ + qbase + r2)*PHD);
    }

    const unsigned char* mkb = mask_l + pairid*128;

#pragma unroll 1
    for (int qi = 0; qi < 16; ++qi) {
        const int q0 = qbase + qi*32;
        // issue pe(qi+1) into stage (qi+1)&1
        if (qi < 15) {
            const uint2* pesrc = g_pe_h + h*NPOS + (992 - (q0 + 32)) + jstart;
            const u32 pedst = smb + (((qi+1) & 1) ? OFF_PE1 : OFF_PE0) + pairid*160*8;
#pragma unroll
            for (int it = 0; it < 3; ++it) {
                int i = tpair + it*64;
                if (i < 160) CPA8(pedst + i*8, pesrc + i);
            }
        }
        CPA_COMMIT();
        CPA_WAITG1();              // pe(qi) (and K/mask on qi==0) complete
        asm volatile("bar.sync %0, 64;" :: "r"(1 + pairid) : "memory");

        const uint2* peb = (const uint2*)(smraw + ((qi & 1) ? OFF_PE1 : OFF_PE0))
                           + pairid*160;

        // p -> half2
        __half2 p1a = __floats2half2_rn(pv1.x, pv1.y);
        __half2 p1b = __floats2half2_rn(pv1.z, pv1.w);
        __half2 p2a = __floats2half2_rn(pv2.x, pv2.y);
        __half2 p2b = __floats2half2_rn(pv2.z, pv2.w);

        float acc[16][4];
#pragma unroll
        for (int t = 0; t < 16; ++t)
#pragma unroll
            for (int i = 0; i < 4; ++i) acc[t][i] = 0.f;

        float s1 = 0.f, s2 = 0.f;

        // ---- fused pipelined loop: MMA(t) overlaps epilogue(t-1) ----
        BFrag bf;
        ld_bfrag(bf, kb2h, kb2l, jstart + g, tig);
#pragma unroll
        for (int t = 0; t < 16; ++t) {
            BFrag cur = bf;
            if (t < 15) ld_bfrag(bf, kb2h, kb2l, jstart + 8*(t+1) + g, tig);
            MMA16816(acc[t], ah[0], ah[1], ah[2], ah[3], cur.h0, cur.h1);
            MMA16816(acc[t], ah[4], ah[5], ah[6], ah[7], cur.h2, cur.h3);
            MMA16816(acc[t], ah[0], ah[1], ah[2], ah[3], cur.l0, cur.l1);
            MMA16816(acc[t], ah[4], ah[5], ah[6], ah[7], cur.l2, cur.l3);
            MMA16816(acc[t], al[0], al[1], al[2], al[3], cur.h0, cur.h1);
            MMA16816(acc[t], al[4], al[5], al[6], al[7], cur.h2, cur.h3);

            if (t > 0) {
                const int e = t - 1;
                const int jl0 = 8*e + 2*tig;
                const int idx1 = jl0 + 31 - r1;
                const int idx2 = idx1 - 8;
                uint2 e11 = peb[idx1];
                uint2 e12 = peb[idx1 + 1];
                uint2 e21 = peb[idx2];
                uint2 e22 = peb[idx2 + 1];
                __half2 q11 = __hfma2(p1a, *(__half2*)&e11.x, __hmul2(p1b, *(__half2*)&e11.y));
                __half2 q12 = __hfma2(p1a, *(__half2*)&e12.x, __hmul2(p1b, *(__half2*)&e12.y));
                __half2 q21 = __hfma2(p2a, *(__half2*)&e21.x, __hmul2(p2b, *(__half2*)&e21.y));
                __half2 q22 = __hfma2(p2a, *(__half2*)&e22.x, __hmul2(p2b, *(__half2*)&e22.y));
                const bool m0 = mkb[jl0] != 0;
                const bool m1 = mkb[jl0 + 1] != 0;
                float e0 = m0 ? 0.f : __expf(acc[e][0] + __low2float(q11) + __high2float(q11));
                float e1 = m1 ? 0.f : __expf(acc[e][1] + __low2float(q12) + __high2float(q12));
                float e2 = m0 ? 0.f : __expf(acc[e][2] + __low2float(q21) + __high2float(q21));
                float e3 = m1 ? 0.f : __expf(acc[e][3] + __low2float(q22) + __high2float(q22));
                acc[e][0] = e0; acc[e][1] = e1; acc[e][2] = e2; acc[e][3] = e3;
                s1 += e0 + e1;
                s2 += e2 + e3;
            }
        }

        // ---- prefetch A/p for qi+1 (latency hidden behind tail+reduction+stores)
        if (qi < 15) {
            const int q0n = q0 + 32;
            const uint4* qa = (const uint4*)(g_qh + (hbSQ + q0n + r1)*16);
            const uint4* qb = (const uint4*)(g_qh + (hbSQ + q0n + r2)*16);
            const uint4* la = (const uint4*)(g_ql + (hbSQ + q0n + r1)*16);
            const uint4* lb = (const uint4*)(g_ql + (hbSQ + q0n + r2)*16);
            uint4 v1 = __ldg(&qa[tig]);
            uint4 v2 = __ldg(&qb[tig]);
            uint4 u1 = __ldg(&la[tig]);
            uint4 u2 = __ldg(&lb[tig]);
            ah[0] = v1.x; ah[1] = v2.x; ah[2] = v1.y; ah[3] = v2.y;
            ah[4] = v1.z; ah[5] = v2.z; ah[6] = v1.w; ah[7] = v2.w;
            al[0] = u1.x; al[1] = u2.x; al[2] = u1.y; al[3] = u2.y;
            al[4] = u1.z; al[5] = u2.z; al[6] = u1.w; al[7] = u2.w;
            pv1 = *(const float4*)(g_p + (hbSQ + q0n + r1)*PHD);
            pv2 = *(const float4*)(g_p + (hbSQ + q0n + r2)*PHD);
        }

        {   // epilogue tile 15
            const int e = 15;
            const int jl0 = 8*e + 2*tig;
            const int idx1 = jl0 + 31 - r1;
            const int idx2 = idx1 - 8;
            uint2 e11 = peb[idx1];
            uint2 e12 = peb[idx1 + 1];
            uint2 e21 = peb[idx2];
            uint2 e22 = peb[idx2 + 1];
            __half2 q11 = __hfma2(p1a, *(__half2*)&e11.x, __hmul2(p1b, *(__half2*)&e11.y));
            __half2 q12 = __hfma2(p1a, *(__half2*)&e12.x, __hmul2(p1b, *(__half2*)&e12.y));
            __half2 q21 = __hfma2(p2a, *(__half2*)&e21.x, __hmul2(p2b, *(__half2*)&e21.y));
            __half2 q22 = __hfma2(p2a, *(__half2*)&e22.x, __hmul2(p2b, *(__half2*)&e22.y));
            const bool m0 = mkb[jl0] != 0;
            const bool m1 = mkb[jl0 + 1] != 0;
            float e0 = m0 ? 0.f : __expf(acc[e][0] + __low2float(q11) + __high2float(q11));
            float e1 = m1 ? 0.f : __expf(acc[e][1] + __low2float(q12) + __high2float(q12));
            float e2 = m0 ? 0.f : __expf(acc[e][2] + __low2float(q21) + __high2float(q21));
            float e3 = m1 ? 0.f : __expf(acc[e][3] + __low2float(q22) + __high2float(q22));
            acc[e][0] = e0; acc[e][1] = e1; acc[e][2] = e2; acc[e][3] = e3;
            s1 += e0 + e1;
            s2 += e2 + e3;
        }

        s1 += __shfl_xor_sync(0xffffffffu, s1, 1);
        s1 += __shfl_xor_sync(0xffffffffu, s1, 2);
        s2 += __shfl_xor_sync(0xffffffffu, s2, 1);
        s2 += __shfl_xor_sync(0xffffffffu, s2, 2);
        if (tig == 0) {
            red_s[r1*8 + pairid] = s1;
            red_s[r2*8 + pairid] = s2;
        }
        __syncthreads();
        if (tid < 32) {
            float s = red_s[tid*8];
#pragma unroll
            for (int i = 1; i < 8; ++i) s += red_s[tid*8 + i];
            inv_s[tid] = 1.0f / s;
        }
        __syncthreads();

        // ---- normalize + streaming float2 stores ----
        const float i1 = inv_s[r1], i2 = inv_s[r2];
        float2* o1 = (float2*)(out + (hbSQ + q0 + r1)*SQ);
        float2* o2 = (float2*)(out + (hbSQ + q0 + r2)*SQ);
#pragma unroll
        for (int t = 0; t < 16; ++t) {
            const int jp = (jstart + 8*t + 2*tig) >> 1;
            float2 v1 = make_float2(acc[t][0] * i1, acc[t][1] * i1);
            float2 v2 = make_float2(acc[t][2] * i2, acc[t][3] * i2);
            __stcs(&o1[jp], v1);
            __stcs(&o2[jp], v2);
        }
    }
}

// ---------------------------------------------------------------------------
extern "C" void kernel_launch(void* const* d_in, const int* in_sizes, int n_in,
                              void* d_out, int out_size)
{
    const float* x            = (const float*)d_in[0];          // (S,B,E)
    const float* pos_emb      = (const float*)d_in[1];          // (1,2S-1,PDIM)
    const unsigned char* kpm  = (const unsigned char*)d_in[2];  // (B,S) bool
    const float* in_proj_w    = (const float*)d_in[3];          // (544,512)
    const float* in_proj_b    = (const float*)d_in[4];          // (544,)
    const float* linear_pos_w = (const float*)d_in[5];          // (32,192)
    float* out = (float*)d_out;                                 // (H,B,S,S)

    static bool attr_set = false;
    if (!attr_set) {
        cudaFuncSetAttribute(attn_kernel,
                             cudaFuncAttributeMaxDynamicSharedMemorySize, SMEM_ATTN);
        cudaFuncSetAttribute(proj_mma_kernel,
                             cudaFuncAttributeMaxDynamicSharedMemorySize, SMEM_PROJ);
        attr_set = true;
    }

    split_prep_kernel<<<(XTOT + WTOT + 255)/256, 256>>>(x, in_proj_w);

    dim3 g1(9, 64);
    proj_mma_kernel<<<g1, 256, SMEM_PROJ>>>(in_proj_b);

    dim3 g2((NPOS + 255)/256, NH);
    pe_kernel<<<g2, 256>>>(pos_emb, linear_pos_w);

    dim3 g3(2, 64);                          // persistent: 128 CTAs, 1/SM
    attn_kernel<<<g3, 512, SMEM_ATTN>>>(kpm, out);
}